// round 12
// baseline (speedup 1.0000x reference)
#include <cuda_runtime.h>
#include <cuda_fp16.h>
#include <math.h>
#include <stdint.h>

// Problem dims
constexpr int BATCH = 2;
constexpr int SEQ   = 1024;
constexpr int DM    = 1024;
constexpr int DIN   = 2048;
constexpr int NST   = 16;
constexpr int FH    = 2752;
constexpr int ROWS  = BATCH * SEQ;  // 2048

// fp32 scratch
__device__ float g_a [ROWS * DIN];    // z (fp32, for scan)
__device__ float g_b [ROWS * DIN];    // dt
__device__ float g_x2[ROWS * DM];
__device__ float g_bc[ROWS * 2 * NST];
__device__ float g_g [ROWS * FH];     // ffn gate preact
__device__ float g_p0[ROWS * DM];     // K-split partials
__device__ float g_p1[ROWS * DM];
// fp16 activations
__device__ __half g_h16[ROWS * DM];
__device__ __half g_a16[ROWS * DIN];
__device__ __half g_y16[ROWS * DIN];
__device__ __half g_g16[ROWS * FH];
// fp16 weights
__device__ __half g_win16 [DIN * DM];
__device__ __half g_wgt16 [DIN * DM];
__device__ __half g_wdt16 [DIN * DIN];
__device__ __half g_wx16  [2 * NST * DIN];
__device__ __half g_wout16[DM * DIN];
__device__ __half g_wfg16 [FH * DM];
__device__ __half g_wfu16 [FH * DM];
__device__ __half g_wfd16 [DM * FH];

constexpr int SW   = 20;             // smem row stride in 4-byte words (32 halfs + 4 pad)
constexpr int ASTG = 128 * SW;       // words per stage per matrix
constexpr int STAGES = 4;

__device__ __forceinline__ uint32_t s2u(const void* p) {
    uint32_t a;
    asm("{ .reg .u64 t; cvta.to.shared.u64 t, %1; cvt.u32.u64 %0, t; }" : "=r"(a) : "l"(p));
    return a;
}
__device__ __forceinline__ void cpa16(uint32_t dst, const __half* src, int szbytes) {
    asm volatile("cp.async.cg.shared.global [%0], [%1], 16, %2;"
                 :: "r"(dst), "l"(src), "r"(szbytes));
}
#define CP_COMMIT() asm volatile("cp.async.commit_group;" ::: "memory")
#define CP_WAIT2()  asm volatile("cp.async.wait_group 2;" ::: "memory")

__device__ __forceinline__ void mma_f16(float c[4],
                                        uint32_t a0, uint32_t a1, uint32_t a2, uint32_t a3,
                                        uint32_t b0, uint32_t b1) {
    asm volatile(
        "mma.sync.aligned.m16n8k16.row.col.f32.f16.f16.f32 "
        "{%0,%1,%2,%3}, {%4,%5,%6,%7}, {%8,%9}, {%0,%1,%2,%3};"
        : "+f"(c[0]), "+f"(c[1]), "+f"(c[2]), "+f"(c[3])
        : "r"(a0), "r"(a1), "r"(a2), "r"(a3), "r"(b0), "r"(b1));
}

enum { EP_NONE = 0, EP_GATEMUL, EP_SOFTPLUS, EP_SILUMUL };

__device__ __forceinline__ float sigm(float x) { return 1.0f / (1.0f + expf(-x)); }
__device__ __forceinline__ float sftp(float x) { return (x > 20.0f) ? x : log1pf(expf(x)); }

// ---------------------------------------------------------------------------
// fp16 GEMM: C = epilogue(A[M,K] @ W[N,K]^T), fp32 accumulate.
// BM=BN=128, BK=32, 256 threads (8 warps, 2x4), warp tile 64x32 (MT=4, NT=4),
// m16n8k16, 4-stage cp.async, forced <=128 regs -> 2 CTAs/SM = 16 warps/SM.
// K-split: P1 != nullptr -> blockIdx.z=1 reads at column offset K, extent K2,
// writes P1.  Folded side-block (last bx, W2 != nullptr): C2 = A@W2^T, N2=32.
// ---------------------------------------------------------------------------
template<int EP>
__global__ void __launch_bounds__(256, 2) gemm_h(
    const __half* __restrict__ A, const __half* __restrict__ W,
    const float* __restrict__ R, const float* __restrict__ bias,
    float* __restrict__ C, __half* __restrict__ C16,
    int M, int N, int K, int K2, int lda, int ldw,
    const __half* __restrict__ W2, float* __restrict__ C2,
    float* __restrict__ P1)
{
    constexpr int MT = 4, NT = 4;
    extern __shared__ uint32_t sm[];
    uint32_t* As = sm;
    uint32_t* Bs = sm + STAGES * ASTG;
    const uint32_t sbA = s2u(As), sbB = s2u(Bs);

    const int tid  = threadIdx.x;
    const int wid  = tid >> 5, lane = tid & 31;
    const int wm   = wid >> 2, wn = wid & 3;
    const int bm   = blockIdx.y << 7;
    const int bx   = blockIdx.x;
    const int bz   = blockIdx.z;
    const int koff = bz * K;
    const int Kext = bz ? K2 : K;
    float* Cw      = (P1 != nullptr && bz == 1) ? P1 : C;
    const bool isbc = (W2 != nullptr) && (bx == (int)gridDim.x - 1);
    const int bn   = isbc ? 0 : (bx << 7);
    const int Nw   = isbc ? 32 : N;
    const __half* Wk = isbc ? W2 : W;
    const int lr   = lane >> 2, lc = lane & 3;

    float acc[MT][NT][4];
    #pragma unroll
    for (int i = 0; i < MT; i++)
        #pragma unroll
        for (int j = 0; j < NT; j++)
            #pragma unroll
            for (int q = 0; q < 4; q++) acc[i][j][q] = 0.0f;

    // Load mapping: 256 threads, stage = 128 rows x 32 halfs; 2 chunks of 16B
    // per thread per matrix.
    const int lrow = tid >> 1;                // 0..127
    const int hw   = (tid & 1) << 4;          // half offset 0 or 16
    const int NS   = Kext >> 5;               // BK = 32

    const __half* abase = A + (size_t)(bm + lrow) * lda + koff + hw;
    const int bv = (bn + lrow < Nw) ? 16 : 0;
    const __half* bbase = Wk + (size_t)min(bn + lrow, Nw - 1) * ldw + koff + hw;
    const uint32_t adst0 = sbA + (uint32_t)((lrow * SW + (hw >> 1)) << 2);
    const uint32_t bdst0 = sbB + (uint32_t)((lrow * SW + (hw >> 1)) << 2);
    constexpr uint32_t STGB = ASTG * 4;

    auto issue = [&](int st, int k0) {
        const uint32_t da = adst0 + st * STGB;
        const uint32_t db = bdst0 + st * STGB;
        cpa16(da,      abase + k0,     16);
        cpa16(da + 16, abase + k0 + 8, 16);
        cpa16(db,      bbase + k0,     bv);
        cpa16(db + 16, bbase + k0 + 8, bv);
        CP_COMMIT();
    };

    issue(0, 0);
    issue(1, 32);
    issue(2, 64);

    const int fa_base = (wm * 64 + lr) * SW + lc;
    const int fb_base = (wn * 32 + lr) * SW + lc;

    for (int ks = 0; ks < NS; ks++) {
        const int buf = ks & 3;
        CP_WAIT2();
        __syncthreads();

        if (ks + 3 < NS) issue((ks + 3) & 3, (ks + 3) << 5);
        else CP_COMMIT();

        const uint32_t* Asb = As + buf * ASTG;
        const uint32_t* Bsb = Bs + buf * ASTG;

        #pragma unroll
        for (int kc = 0; kc < 2; kc++) {       // two k16 steps per BK=32
            const int kp = kc * 8;
            uint32_t af[MT][4], bf[NT][2];
            #pragma unroll
            for (int tm = 0; tm < MT; tm++) {
                const int base = fa_base + tm * 16 * SW + kp;
                af[tm][0] = Asb[base];
                af[tm][1] = Asb[base + 8 * SW];
                af[tm][2] = Asb[base + 4];
                af[tm][3] = Asb[base + 8 * SW + 4];
            }
            #pragma unroll
            for (int tn = 0; tn < NT; tn++) {
                const int base = fb_base + tn * 8 * SW + kp;
                bf[tn][0] = Bsb[base];
                bf[tn][1] = Bsb[base + 4];
            }
            #pragma unroll
            for (int tm = 0; tm < MT; tm++)
                #pragma unroll
                for (int tn = 0; tn < NT; tn++)
                    mma_f16(acc[tm][tn], af[tm][0], af[tm][1], af[tm][2], af[tm][3],
                            bf[tn][0], bf[tn][1]);
        }
    }

    if (isbc) {
        #pragma unroll
        for (int tm = 0; tm < MT; tm++) {
            const int row = bm + wm * 64 + tm * 16 + lr;
            #pragma unroll
            for (int tn = 0; tn < NT; tn++) {
                const int col = wn * 32 + tn * 8 + lc * 2;
                if (col < 32) {
                    *(float2*)(C2 + (size_t)row * 32 + col) =
                        make_float2(acc[tm][tn][0], acc[tm][tn][1]);
                    *(float2*)(C2 + (size_t)(row + 8) * 32 + col) =
                        make_float2(acc[tm][tn][2], acc[tm][tn][3]);
                }
            }
        }
        return;
    }

    #pragma unroll
    for (int tm = 0; tm < MT; tm++) {
        const int row = bm + wm * 64 + tm * 16 + lr;
        #pragma unroll
        for (int tn = 0; tn < NT; tn++) {
            const int col = bn + wn * 32 + tn * 8 + lc * 2;
            if (col < N) {
                #pragma unroll
                for (int hf = 0; hf < 2; hf++) {
                    const size_t o = (size_t)(row + hf * 8) * N + col;
                    float v0 = acc[tm][tn][hf * 2], v1 = acc[tm][tn][hf * 2 + 1];
                    if (EP == EP_NONE) {
                        *(float2*)(Cw + o) = make_float2(v0, v1);
                    } else if (EP == EP_GATEMUL) {
                        const float2 r = *(const float2*)(R + o);
                        v0 = r.x * sigm(v0); v1 = r.y * sigm(v1);
                        *(float2*)(C + o) = make_float2(v0, v1);
                        *(__half2*)(C16 + o) = __floats2half2_rn(v0, v1);
                    } else if (EP == EP_SOFTPLUS) {
                        const float2 bv2 = *(const float2*)(bias + col);
                        *(float2*)(C + o) = make_float2(sftp(v0 + bv2.x), sftp(v1 + bv2.y));
                    } else if (EP == EP_SILUMUL) {
                        const float2 r = *(const float2*)(R + o);
                        v0 = r.x * sigm(r.x) * v0; v1 = r.y * sigm(r.y) * v1;
                        *(__half2*)(C16 + o) = __floats2half2_rn(v0, v1);
                    }
                }
            }
        }
    }
}

// ---------------------------------------------------------------------------
// Fused fp32->fp16 conversion of all 8 weight matrices in one launch.
// ---------------------------------------------------------------------------
struct CvtJobs {
    const float4* src[8];
    __half2* dst[8];
    int cum[9];
};

__global__ void __launch_bounds__(256) cvt_all_kernel(CvtJobs jobs)
{
    int i = blockIdx.x * 256 + threadIdx.x;
    if (i >= jobs.cum[8]) return;
    int j = 0;
    #pragma unroll
    for (int t = 1; t < 8; t++) j += (i >= jobs.cum[t]);
    const int li = i - jobs.cum[j];
    const float4 v = jobs.src[j][li];
    jobs.dst[j][2 * li]     = __floats2half2_rn(v.x, v.y);
    jobs.dst[j][2 * li + 1] = __floats2half2_rn(v.z, v.w);
}

// ---------------------------------------------------------------------------
// RMSNorm -> fp16 output
// ---------------------------------------------------------------------------
__global__ void __launch_bounds__(256) rmsnorm16_kernel(
    const float* __restrict__ x, const float* __restrict__ w, __half* __restrict__ out)
{
    __shared__ float red[8];
    const int row = blockIdx.x;
    const int tid = threadIdx.x;
    const float4 v = ((const float4*)(x + (size_t)row * DM))[tid];
    float s = v.x*v.x + v.y*v.y + v.z*v.z + v.w*v.w;
    #pragma unroll
    for (int o = 16; o; o >>= 1) s += __shfl_xor_sync(0xffffffffu, s, o);
    if ((tid & 31) == 0) red[tid >> 5] = s;
    __syncthreads();
    if (tid < 8) {
        float t = red[tid];
        #pragma unroll
        for (int o = 4; o; o >>= 1) t += __shfl_xor_sync(0xffu, t, o);
        if (tid == 0) red[0] = t;
    }
    __syncthreads();
    const float scale = rsqrtf(red[0] * (1.0f / DM) + 1e-6f);
    const float4 wv = ((const float4*)w)[tid];
    __half2* op = (__half2*)(out + (size_t)row * DM) + tid * 2;
    op[0] = __floats2half2_rn(v.x * scale * wv.x, v.y * scale * wv.y);
    op[1] = __floats2half2_rn(v.z * scale * wv.z, v.w * scale * wv.w);
}

// ---------------------------------------------------------------------------
// x2 = x + p0 + p1 ; h16 = fp16(rmsnorm(x2, w))
// ---------------------------------------------------------------------------
__global__ void __launch_bounds__(256) combine_norm_kernel(
    const float* __restrict__ x, const float* __restrict__ w,
    float* __restrict__ x2, __half* __restrict__ h16)
{
    __shared__ float red[8];
    const int row = blockIdx.x;
    const int tid = threadIdx.x;
    const size_t o = (size_t)row * DM / 4 + tid;
    const float4 xv = ((const float4*)x)[o];
    const float4 p0 = ((const float4*)g_p0)[o];
    const float4 p1 = ((const float4*)g_p1)[o];
    float4 v;
    v.x = xv.x + p0.x + p1.x; v.y = xv.y + p0.y + p1.y;
    v.z = xv.z + p0.z + p1.z; v.w = xv.w + p0.w + p1.w;
    ((float4*)x2)[o] = v;
    float s = v.x*v.x + v.y*v.y + v.z*v.z + v.w*v.w;
    #pragma unroll
    for (int of = 16; of; of >>= 1) s += __shfl_xor_sync(0xffffffffu, s, of);
    if ((tid & 31) == 0) red[tid >> 5] = s;
    __syncthreads();
    if (tid < 8) {
        float t = red[tid];
        #pragma unroll
        for (int of = 4; of; of >>= 1) t += __shfl_xor_sync(0xffu, t, of);
        if (tid == 0) red[0] = t;
    }
    __syncthreads();
    const float scale = rsqrtf(red[0] * (1.0f / DM) + 1e-6f);
    const float4 wv = ((const float4*)w)[tid];
    __half2* op = (__half2*)(h16 + (size_t)row * DM) + tid * 2;
    op[0] = __floats2half2_rn(v.x * scale * wv.x, v.y * scale * wv.y);
    op[1] = __floats2half2_rn(v.z * scale * wv.z, v.w * scale * wv.w);
}

// out = x2 + p0 + p1
__global__ void __launch_bounds__(256) combine_add_kernel(
    const float* __restrict__ x2, float* __restrict__ out)
{
    const size_t i = (size_t)blockIdx.x * 256 + threadIdx.x;
    const float4 a = ((const float4*)x2)[i];
    const float4 p0 = ((const float4*)g_p0)[i];
    const float4 p1 = ((const float4*)g_p1)[i];
    float4 v;
    v.x = a.x + p0.x + p1.x; v.y = a.y + p0.y + p1.y;
    v.z = a.z + p0.z + p1.z; v.w = a.w + p0.w + p1.w;
    ((float4*)out)[i] = v;
}

// ---------------------------------------------------------------------------
// Selective scan (16 lanes per channel) -> y16 fp16
// ---------------------------------------------------------------------------
__global__ void __launch_bounds__(256) scan_kernel(
    const float* __restrict__ A_log, const float* __restrict__ Dp)
{
    const int tid = threadIdx.x;
    const int ch  = blockIdx.x * 16 + (tid >> 4);
    const int n   = tid & 15;
    const int b   = ch / DIN;
    const int e   = ch % DIN;

    const float An  = -__expf(A_log[(size_t)e * NST + n]);
    const float dpe = Dp[e];

    const float* dtp = g_b  + (size_t)b * SEQ * DIN + e;
    const float* zp  = g_a  + (size_t)b * SEQ * DIN + e;
    const float* bcp = g_bc + (size_t)b * SEQ * 32;
    __half*      yp  = g_y16 + (size_t)b * SEQ * DIN + e;

    float state = 0.0f;
    #pragma unroll 4
    for (int t = 0; t < SEQ; t++) {
        const float dtv = __ldg(dtp + (size_t)t * DIN);
        const float zv  = __ldg(zp  + (size_t)t * DIN);
        const float Bn  = bcp[t * 32 + n];
        const float Cn  = bcp[t * 32 + 16 + n];
        state = __expf(dtv * An) * state + dtv * zv * Bn;
        float s = state * Cn;
        s += __shfl_xor_sync(0xffffffffu, s, 8);
        s += __shfl_xor_sync(0xffffffffu, s, 4);
        s += __shfl_xor_sync(0xffffffffu, s, 2);
        s += __shfl_xor_sync(0xffffffffu, s, 1);
        if (n == 0) yp[(size_t)t * DIN] = __float2half_rn(s + zv * dpe);
    }
}

// ---------------------------------------------------------------------------
// Launch
// ---------------------------------------------------------------------------
extern "C" void kernel_launch(void* const* d_in, const int* in_sizes, int n_in,
                              void* d_out, int out_size)
{
    const float* x          = (const float*)d_in[0];
    const float* norm1_w    = (const float*)d_in[1];
    const float* in_proj_w  = (const float*)d_in[2];
    const float* gate_proj_w= (const float*)d_in[3];
    const float* dt_w       = (const float*)d_in[4];
    const float* dt_b       = (const float*)d_in[5];
    const float* x_proj_w   = (const float*)d_in[6];
    const float* A_log      = (const float*)d_in[7];
    const float* Dp         = (const float*)d_in[8];
    const float* out_proj_w = (const float*)d_in[9];
    const float* ffn_norm_w = (const float*)d_in[10];
    const float* ffn_gate_w = (const float*)d_in[11];
    const float* ffn_up_w   = (const float*)d_in[12];
    const float* ffn_down_w = (const float*)d_in[13];
    float* out = (float*)d_out;

    float *a, *bb, *x2, *gg, *bc, *p0, *p1;
    __half *h16, *a16, *y16, *g16;
    __half *win, *wgt, *wdt, *wx, *wout, *wfg, *wfu, *wfd;
    cudaGetSymbolAddress((void**)&a,   g_a);
    cudaGetSymbolAddress((void**)&bb,  g_b);
    cudaGetSymbolAddress((void**)&x2,  g_x2);
    cudaGetSymbolAddress((void**)&gg,  g_g);
    cudaGetSymbolAddress((void**)&bc,  g_bc);
    cudaGetSymbolAddress((void**)&p0,  g_p0);
    cudaGetSymbolAddress((void**)&p1,  g_p1);
    cudaGetSymbolAddress((void**)&h16, g_h16);
    cudaGetSymbolAddress((void**)&a16, g_a16);
    cudaGetSymbolAddress((void**)&y16, g_y16);
    cudaGetSymbolAddress((void**)&g16, g_g16);
    cudaGetSymbolAddress((void**)&win, g_win16);
    cudaGetSymbolAddress((void**)&wgt, g_wgt16);
    cudaGetSymbolAddress((void**)&wdt, g_wdt16);
    cudaGetSymbolAddress((void**)&wx,  g_wx16);
    cudaGetSymbolAddress((void**)&wout,g_wout16);
    cudaGetSymbolAddress((void**)&wfg, g_wfg16);
    cudaGetSymbolAddress((void**)&wfu, g_wfu16);
    cudaGetSymbolAddress((void**)&wfd, g_wfd16);

    const int SMEM = STAGES * ASTG * 4 * 2;   // 81920 bytes

    cudaFuncSetAttribute((const void*)gemm_h<EP_NONE>,     cudaFuncAttributeMaxDynamicSharedMemorySize, SMEM);
    cudaFuncSetAttribute((const void*)gemm_h<EP_GATEMUL>,  cudaFuncAttributeMaxDynamicSharedMemorySize, SMEM);
    cudaFuncSetAttribute((const void*)gemm_h<EP_SOFTPLUS>, cudaFuncAttributeMaxDynamicSharedMemorySize, SMEM);
    cudaFuncSetAttribute((const void*)gemm_h<EP_SILUMUL>,  cudaFuncAttributeMaxDynamicSharedMemorySize, SMEM);

    const dim3 blk256(256);

    // 0. Convert all weights to fp16 in one launch
    {
        CvtJobs jobs;
        const float* srcs[8] = {in_proj_w, gate_proj_w, dt_w, x_proj_w,
                                out_proj_w, ffn_gate_w, ffn_up_w, ffn_down_w};
        __half* dsts[8] = {win, wgt, wdt, wx, wout, wfg, wfu, wfd};
        const int ns[8] = {DIN*DM, DIN*DM, DIN*DIN, 2*NST*DIN,
                           DM*DIN, FH*DM, FH*DM, DM*FH};
        int cum = 0;
        for (int j = 0; j < 8; j++) {
            jobs.src[j] = (const float4*)srcs[j];
            jobs.dst[j] = (__half2*)dsts[j];
            jobs.cum[j] = cum;
            cum += ns[j] / 4;
        }
        jobs.cum[8] = cum;
        cvt_all_kernel<<<(cum + 255) / 256, blk256>>>(jobs);
    }

    // 1. h16 = fp16(rmsnorm(x))
    rmsnorm16_kernel<<<ROWS, blk256>>>(x, norm1_w, h16);

    // 2. a = h @ in_proj^T ; z = a * sigmoid(h @ gate_proj^T) -> a (fp32) + a16
    gemm_h<EP_NONE>   <<<dim3(DIN/128, ROWS/128), blk256, SMEM>>>(h16, win, nullptr, nullptr, a,  nullptr, ROWS, DIN, DM, 0, DM, DM, nullptr, nullptr, nullptr);
    gemm_h<EP_GATEMUL><<<dim3(DIN/128, ROWS/128), blk256, SMEM>>>(h16, wgt, a,       nullptr, a,  a16,     ROWS, DIN, DM, 0, DM, DM, nullptr, nullptr, nullptr);

    // 3. dt = softplus(z @ dt_w^T + dt_b)  [+ folded BC = z @ x_proj^T]
    gemm_h<EP_SOFTPLUS><<<dim3(DIN/128 + 1, ROWS/128), blk256, SMEM>>>(a16, wdt, nullptr, dt_b, bb, nullptr, ROWS, DIN, DIN, 0, DIN, DIN, wx, bc, nullptr);

    // 4. scan -> y16
    scan_kernel<<<(BATCH * DIN) / 16, blk256>>>(A_log, Dp);

    // 5. p0/p1 = y @ out_proj^T (K-split); x2 = x + p0 + p1 ; h16 = fp16(rmsnorm(x2))
    gemm_h<EP_NONE><<<dim3(DM/128, ROWS/128, 2), blk256, SMEM>>>(y16, wout, nullptr, nullptr, p0, nullptr, ROWS, DM, DIN/2, DIN/2, DIN, DIN, nullptr, nullptr, p1);
    combine_norm_kernel<<<ROWS, blk256>>>(x, ffn_norm_w, x2, h16);

    // 6. FFN: gg = hn @ Wg^T ; g16 = fp16(silu(gg) * (hn @ Wu^T))
    gemm_h<EP_NONE>   <<<dim3((FH+127)/128, ROWS/128), blk256, SMEM>>>(h16, wfg, nullptr, nullptr, gg, nullptr, ROWS, FH, DM, 0, DM, DM, nullptr, nullptr, nullptr);
    gemm_h<EP_SILUMUL><<<dim3((FH+127)/128, ROWS/128), blk256, SMEM>>>(h16, wfu, gg,      nullptr, nullptr, g16, ROWS, FH, DM, 0, DM, DM, nullptr, nullptr, nullptr);

    // 7. p0/p1 = g16 @ Wd^T (uneven K-split 1408/1344); out = x2 + p0 + p1
    gemm_h<EP_NONE><<<dim3(DM/128, ROWS/128, 2), blk256, SMEM>>>(g16, wfd, nullptr, nullptr, p0, nullptr, ROWS, DM, 1408, 1344, FH, FH, nullptr, nullptr, p1);
    combine_add_kernel<<<(ROWS * DM) / 1024, blk256>>>(x2, out);
}

// round 13
// speedup vs baseline: 1.0637x; 1.0637x over previous
#include <cuda_runtime.h>
#include <cuda_fp16.h>
#include <math.h>
#include <stdint.h>

// Problem dims
constexpr int BATCH = 2;
constexpr int SEQ   = 1024;
constexpr int DM    = 1024;
constexpr int DIN   = 2048;
constexpr int NST   = 16;
constexpr int FH    = 2752;
constexpr int ROWS  = BATCH * SEQ;  // 2048

// fp32 scratch
__device__ float g_a [ROWS * DIN];
__device__ float g_b [ROWS * DIN];
__device__ float g_x2[ROWS * DM];
__device__ float g_bc[ROWS * 2 * NST];
__device__ float g_g [ROWS * FH];
__device__ float g_p0[ROWS * DM];
__device__ float g_p1[ROWS * DM];
// fp16 activations
__device__ __half g_h16[ROWS * DM];
__device__ __half g_a16[ROWS * DIN];
__device__ __half g_y16[ROWS * DIN];
__device__ __half g_g16[ROWS * FH];
// fp16 weights
__device__ __half g_win16 [DIN * DM];
__device__ __half g_wgt16 [DIN * DM];
__device__ __half g_wdt16 [DIN * DIN];
__device__ __half g_wx16  [2 * NST * DIN];
__device__ __half g_wout16[DM * DIN];
__device__ __half g_wfg16 [FH * DM];
__device__ __half g_wfu16 [FH * DM];
__device__ __half g_wfd16 [DM * FH];

constexpr int SW   = 20;             // smem row stride in 4-byte words
constexpr int ASTG = 128 * SW;
constexpr int STAGES = 4;

__device__ __forceinline__ uint32_t s2u(const void* p) {
    uint32_t a;
    asm("{ .reg .u64 t; cvta.to.shared.u64 t, %1; cvt.u32.u64 %0, t; }" : "=r"(a) : "l"(p));
    return a;
}
__device__ __forceinline__ void cpa16(uint32_t dst, const __half* src, int szbytes) {
    asm volatile("cp.async.cg.shared.global [%0], [%1], 16, %2;"
                 :: "r"(dst), "l"(src), "r"(szbytes));
}
#define CP_COMMIT() asm volatile("cp.async.commit_group;" ::: "memory")
#define CP_WAIT2()  asm volatile("cp.async.wait_group 2;" ::: "memory")

__device__ __forceinline__ void mma_f16(float c[4],
                                        uint32_t a0, uint32_t a1, uint32_t a2, uint32_t a3,
                                        uint32_t b0, uint32_t b1) {
    asm volatile(
        "mma.sync.aligned.m16n8k16.row.col.f32.f16.f16.f32 "
        "{%0,%1,%2,%3}, {%4,%5,%6,%7}, {%8,%9}, {%0,%1,%2,%3};"
        : "+f"(c[0]), "+f"(c[1]), "+f"(c[2]), "+f"(c[3])
        : "r"(a0), "r"(a1), "r"(a2), "r"(a3), "r"(b0), "r"(b1));
}
#define LDSM4(r0, r1, r2, r3, addr) \
    asm volatile("ldmatrix.sync.aligned.m8n8.x4.shared.b16 {%0,%1,%2,%3}, [%4];" \
        : "=r"(r0), "=r"(r1), "=r"(r2), "=r"(r3) : "r"(addr))

enum { EP_NONE = 0, EP_GATEMUL, EP_SOFTPLUS, EP_SILUMUL };

__device__ __forceinline__ float sigm(float x) { return 1.0f / (1.0f + expf(-x)); }
__device__ __forceinline__ float sftp(float x) { return (x > 20.0f) ? x : log1pf(expf(x)); }

// ---------------------------------------------------------------------------
// fp16 GEMM with ldmatrix fragment loads.
// BM=BN=128, BK=32, 256 threads (8 warps 2x4), warp tile 64x32 (MT=4, NT=4),
// m16n8k16, 4-stage cp.async, 2 CTAs/SM.
// ---------------------------------------------------------------------------
template<int EP>
__global__ void __launch_bounds__(256, 2) gemm_h(
    const __half* __restrict__ A, const __half* __restrict__ W,
    const float* __restrict__ R, const float* __restrict__ bias,
    float* __restrict__ C, __half* __restrict__ C16,
    int M, int N, int K, int K2, int lda, int ldw,
    const __half* __restrict__ W2, float* __restrict__ C2,
    float* __restrict__ P1)
{
    constexpr int MT = 4, NT = 4;
    extern __shared__ uint32_t sm[];
    uint32_t* As = sm;
    uint32_t* Bs = sm + STAGES * ASTG;
    const uint32_t sbA = s2u(As), sbB = s2u(Bs);

    const int tid  = threadIdx.x;
    const int wid  = tid >> 5, lane = tid & 31;
    const int wm   = wid >> 2, wn = wid & 3;
    const int bm   = blockIdx.y << 7;
    const int bx   = blockIdx.x;
    const int bz   = blockIdx.z;
    const int koff = bz * K;
    const int Kext = bz ? K2 : K;
    float* Cw      = (P1 != nullptr && bz == 1) ? P1 : C;
    const bool isbc = (W2 != nullptr) && (bx == (int)gridDim.x - 1);
    const int bn   = isbc ? 0 : (bx << 7);
    const int Nw   = isbc ? 32 : N;
    const __half* Wk = isbc ? W2 : W;
    const int lr   = lane >> 2, lc = lane & 3;

    float acc[MT][NT][4];
    #pragma unroll
    for (int i = 0; i < MT; i++)
        #pragma unroll
        for (int j = 0; j < NT; j++)
            #pragma unroll
            for (int q = 0; q < 4; q++) acc[i][j][q] = 0.0f;

    const int lrow = tid >> 1;
    const int hw   = (tid & 1) << 4;
    const int NS   = Kext >> 5;               // BK = 32

    const __half* abase = A + (size_t)(bm + lrow) * lda + koff + hw;
    const int bv = (bn + lrow < Nw) ? 16 : 0;
    const __half* bbase = Wk + (size_t)min(bn + lrow, Nw - 1) * ldw + koff + hw;
    const uint32_t adst0 = sbA + (uint32_t)((lrow * SW + (hw >> 1)) << 2);
    const uint32_t bdst0 = sbB + (uint32_t)((lrow * SW + (hw >> 1)) << 2);
    constexpr uint32_t STGB = ASTG * 4;

    auto issue = [&](int st, int k0) {
        const uint32_t da = adst0 + st * STGB;
        const uint32_t db = bdst0 + st * STGB;
        cpa16(da,      abase + k0,     16);
        cpa16(da + 16, abase + k0 + 8, 16);
        cpa16(db,      bbase + k0,     bv);
        cpa16(db + 16, bbase + k0 + 8, bv);
        CP_COMMIT();
    };

    issue(0, 0);
    issue(1, 32);
    issue(2, 64);

    // ldmatrix per-lane base offsets (bytes)
    const int arow = lane & 15;
    const int acol = (lane >> 4) << 2;                 // +16B chunk
    const uint32_t aoff = (uint32_t)(((wm * 64 + arow) * SW + acol) << 2);
    const int brow = (lane & 7) + ((lane >> 4) << 3);
    const int bcol = ((lane >> 3) & 1) << 2;
    const uint32_t boff = (uint32_t)(((wn * 32 + brow) * SW + bcol) << 2);
    constexpr uint32_t TMSTR = 16 * SW * 4;            // 16-row tile stride (bytes)

    for (int ks = 0; ks < NS; ks++) {
        const int buf = ks & 3;
        CP_WAIT2();
        __syncthreads();

        if (ks + 3 < NS) issue((ks + 3) & 3, (ks + 3) << 5);
        else CP_COMMIT();

        const uint32_t Abase = sbA + buf * STGB + aoff;
        const uint32_t Bbase = sbB + buf * STGB + boff;

        #pragma unroll
        for (int kc = 0; kc < 2; kc++) {       // two k16 steps per BK=32
            uint32_t af[MT][4], bf[NT][2];
            #pragma unroll
            for (int tm = 0; tm < MT; tm++)
                LDSM4(af[tm][0], af[tm][1], af[tm][2], af[tm][3],
                      Abase + tm * TMSTR + kc * 32);
            #pragma unroll
            for (int tp = 0; tp < 2; tp++)
                LDSM4(bf[2*tp][0], bf[2*tp][1], bf[2*tp+1][0], bf[2*tp+1][1],
                      Bbase + tp * TMSTR + kc * 32);
            #pragma unroll
            for (int tm = 0; tm < MT; tm++)
                #pragma unroll
                for (int tn = 0; tn < NT; tn++)
                    mma_f16(acc[tm][tn], af[tm][0], af[tm][1], af[tm][2], af[tm][3],
                            bf[tn][0], bf[tn][1]);
        }
    }

    if (isbc) {
        #pragma unroll
        for (int tm = 0; tm < MT; tm++) {
            const int row = bm + wm * 64 + tm * 16 + lr;
            #pragma unroll
            for (int tn = 0; tn < NT; tn++) {
                const int col = wn * 32 + tn * 8 + lc * 2;
                if (col < 32) {
                    *(float2*)(C2 + (size_t)row * 32 + col) =
                        make_float2(acc[tm][tn][0], acc[tm][tn][1]);
                    *(float2*)(C2 + (size_t)(row + 8) * 32 + col) =
                        make_float2(acc[tm][tn][2], acc[tm][tn][3]);
                }
            }
        }
        return;
    }

    #pragma unroll
    for (int tm = 0; tm < MT; tm++) {
        const int row = bm + wm * 64 + tm * 16 + lr;
        #pragma unroll
        for (int tn = 0; tn < NT; tn++) {
            const int col = bn + wn * 32 + tn * 8 + lc * 2;
            if (col < N) {
                #pragma unroll
                for (int hf = 0; hf < 2; hf++) {
                    const size_t o = (size_t)(row + hf * 8) * N + col;
                    float v0 = acc[tm][tn][hf * 2], v1 = acc[tm][tn][hf * 2 + 1];
                    if (EP == EP_NONE) {
                        *(float2*)(Cw + o) = make_float2(v0, v1);
                    } else if (EP == EP_GATEMUL) {
                        const float2 r = *(const float2*)(R + o);
                        v0 = r.x * sigm(v0); v1 = r.y * sigm(v1);
                        *(float2*)(C + o) = make_float2(v0, v1);
                        *(__half2*)(C16 + o) = __floats2half2_rn(v0, v1);
                    } else if (EP == EP_SOFTPLUS) {
                        const float2 bv2 = *(const float2*)(bias + col);
                        *(float2*)(C + o) = make_float2(sftp(v0 + bv2.x), sftp(v1 + bv2.y));
                    } else if (EP == EP_SILUMUL) {
                        const float2 r = *(const float2*)(R + o);
                        v0 = r.x * sigm(r.x) * v0; v1 = r.y * sigm(r.y) * v1;
                        *(__half2*)(C16 + o) = __floats2half2_rn(v0, v1);
                    }
                }
            }
        }
    }
}

// ---------------------------------------------------------------------------
// Fused fp32->fp16 conversion of all 8 weight matrices in one launch.
// ---------------------------------------------------------------------------
struct CvtJobs {
    const float4* src[8];
    __half2* dst[8];
    int cum[9];
};

__global__ void __launch_bounds__(256) cvt_all_kernel(CvtJobs jobs)
{
    int i = blockIdx.x * 256 + threadIdx.x;
    if (i >= jobs.cum[8]) return;
    int j = 0;
    #pragma unroll
    for (int t = 1; t < 8; t++) j += (i >= jobs.cum[t]);
    const int li = i - jobs.cum[j];
    const float4 v = jobs.src[j][li];
    jobs.dst[j][2 * li]     = __floats2half2_rn(v.x, v.y);
    jobs.dst[j][2 * li + 1] = __floats2half2_rn(v.z, v.w);
}

// ---------------------------------------------------------------------------
// RMSNorm -> fp16 output
// ---------------------------------------------------------------------------
__global__ void __launch_bounds__(256) rmsnorm16_kernel(
    const float* __restrict__ x, const float* __restrict__ w, __half* __restrict__ out)
{
    __shared__ float red[8];
    const int row = blockIdx.x;
    const int tid = threadIdx.x;
    const float4 v = ((const float4*)(x + (size_t)row * DM))[tid];
    float s = v.x*v.x + v.y*v.y + v.z*v.z + v.w*v.w;
    #pragma unroll
    for (int o = 16; o; o >>= 1) s += __shfl_xor_sync(0xffffffffu, s, o);
    if ((tid & 31) == 0) red[tid >> 5] = s;
    __syncthreads();
    if (tid < 8) {
        float t = red[tid];
        #pragma unroll
        for (int o = 4; o; o >>= 1) t += __shfl_xor_sync(0xffu, t, o);
        if (tid == 0) red[0] = t;
    }
    __syncthreads();
    const float scale = rsqrtf(red[0] * (1.0f / DM) + 1e-6f);
    const float4 wv = ((const float4*)w)[tid];
    __half2* op = (__half2*)(out + (size_t)row * DM) + tid * 2;
    op[0] = __floats2half2_rn(v.x * scale * wv.x, v.y * scale * wv.y);
    op[1] = __floats2half2_rn(v.z * scale * wv.z, v.w * scale * wv.w);
}

// ---------------------------------------------------------------------------
// x2 = x + p0 + p1 ; h16 = fp16(rmsnorm(x2, w))
// ---------------------------------------------------------------------------
__global__ void __launch_bounds__(256) combine_norm_kernel(
    const float* __restrict__ x, const float* __restrict__ w,
    float* __restrict__ x2, __half* __restrict__ h16)
{
    __shared__ float red[8];
    const int row = blockIdx.x;
    const int tid = threadIdx.x;
    const size_t o = (size_t)row * DM / 4 + tid;
    const float4 xv = ((const float4*)x)[o];
    const float4 p0 = ((const float4*)g_p0)[o];
    const float4 p1 = ((const float4*)g_p1)[o];
    float4 v;
    v.x = xv.x + p0.x + p1.x; v.y = xv.y + p0.y + p1.y;
    v.z = xv.z + p0.z + p1.z; v.w = xv.w + p0.w + p1.w;
    ((float4*)x2)[o] = v;
    float s = v.x*v.x + v.y*v.y + v.z*v.z + v.w*v.w;
    #pragma unroll
    for (int of = 16; of; of >>= 1) s += __shfl_xor_sync(0xffffffffu, s, of);
    if ((tid & 31) == 0) red[tid >> 5] = s;
    __syncthreads();
    if (tid < 8) {
        float t = red[tid];
        #pragma unroll
        for (int of = 4; of; of >>= 1) t += __shfl_xor_sync(0xffu, t, of);
        if (tid == 0) red[0] = t;
    }
    __syncthreads();
    const float scale = rsqrtf(red[0] * (1.0f / DM) + 1e-6f);
    const float4 wv = ((const float4*)w)[tid];
    __half2* op = (__half2*)(h16 + (size_t)row * DM) + tid * 2;
    op[0] = __floats2half2_rn(v.x * scale * wv.x, v.y * scale * wv.y);
    op[1] = __floats2half2_rn(v.z * scale * wv.z, v.w * scale * wv.w);
}

// out = x2 + p0 + p1
__global__ void __launch_bounds__(256) combine_add_kernel(
    const float* __restrict__ x2, float* __restrict__ out)
{
    const size_t i = (size_t)blockIdx.x * 256 + threadIdx.x;
    const float4 a = ((const float4*)x2)[i];
    const float4 p0 = ((const float4*)g_p0)[i];
    const float4 p1 = ((const float4*)g_p1)[i];
    float4 v;
    v.x = a.x + p0.x + p1.x; v.y = a.y + p0.y + p1.y;
    v.z = a.z + p0.z + p1.z; v.w = a.w + p0.w + p1.w;
    ((float4*)out)[i] = v;
}

// ---------------------------------------------------------------------------
// Selective scan (16 lanes per channel) -> y16 fp16
// ---------------------------------------------------------------------------
__global__ void __launch_bounds__(256) scan_kernel(
    const float* __restrict__ A_log, const float* __restrict__ Dp)
{
    const int tid = threadIdx.x;
    const int ch  = blockIdx.x * 16 + (tid >> 4);
    const int n   = tid & 15;
    const int b   = ch / DIN;
    const int e   = ch % DIN;

    const float An  = -__expf(A_log[(size_t)e * NST + n]);
    const float dpe = Dp[e];

    const float* dtp = g_b  + (size_t)b * SEQ * DIN + e;
    const float* zp  = g_a  + (size_t)b * SEQ * DIN + e;
    const float* bcp = g_bc + (size_t)b * SEQ * 32;
    __half*      yp  = g_y16 + (size_t)b * SEQ * DIN + e;

    float state = 0.0f;
    #pragma unroll 4
    for (int t = 0; t < SEQ; t++) {
        const float dtv = __ldg(dtp + (size_t)t * DIN);
        const float zv  = __ldg(zp  + (size_t)t * DIN);
        const float Bn  = bcp[t * 32 + n];
        const float Cn  = bcp[t * 32 + 16 + n];
        state = __expf(dtv * An) * state + dtv * zv * Bn;
        float s = state * Cn;
        s += __shfl_xor_sync(0xffffffffu, s, 8);
        s += __shfl_xor_sync(0xffffffffu, s, 4);
        s += __shfl_xor_sync(0xffffffffu, s, 2);
        s += __shfl_xor_sync(0xffffffffu, s, 1);
        if (n == 0) yp[(size_t)t * DIN] = __float2half_rn(s + zv * dpe);
    }
}

// ---------------------------------------------------------------------------
// Launch
// ---------------------------------------------------------------------------
extern "C" void kernel_launch(void* const* d_in, const int* in_sizes, int n_in,
                              void* d_out, int out_size)
{
    const float* x          = (const float*)d_in[0];
    const float* norm1_w    = (const float*)d_in[1];
    const float* in_proj_w  = (const float*)d_in[2];
    const float* gate_proj_w= (const float*)d_in[3];
    const float* dt_w       = (const float*)d_in[4];
    const float* dt_b       = (const float*)d_in[5];
    const float* x_proj_w   = (const float*)d_in[6];
    const float* A_log      = (const float*)d_in[7];
    const float* Dp         = (const float*)d_in[8];
    const float* out_proj_w = (const float*)d_in[9];
    const float* ffn_norm_w = (const float*)d_in[10];
    const float* ffn_gate_w = (const float*)d_in[11];
    const float* ffn_up_w   = (const float*)d_in[12];
    const float* ffn_down_w = (const float*)d_in[13];
    float* out = (float*)d_out;

    float *a, *bb, *x2, *gg, *bc, *p0, *p1;
    __half *h16, *a16, *y16, *g16;
    __half *win, *wgt, *wdt, *wx, *wout, *wfg, *wfu, *wfd;
    cudaGetSymbolAddress((void**)&a,   g_a);
    cudaGetSymbolAddress((void**)&bb,  g_b);
    cudaGetSymbolAddress((void**)&x2,  g_x2);
    cudaGetSymbolAddress((void**)&gg,  g_g);
    cudaGetSymbolAddress((void**)&bc,  g_bc);
    cudaGetSymbolAddress((void**)&p0,  g_p0);
    cudaGetSymbolAddress((void**)&p1,  g_p1);
    cudaGetSymbolAddress((void**)&h16, g_h16);
    cudaGetSymbolAddress((void**)&a16, g_a16);
    cudaGetSymbolAddress((void**)&y16, g_y16);
    cudaGetSymbolAddress((void**)&g16, g_g16);
    cudaGetSymbolAddress((void**)&win, g_win16);
    cudaGetSymbolAddress((void**)&wgt, g_wgt16);
    cudaGetSymbolAddress((void**)&wdt, g_wdt16);
    cudaGetSymbolAddress((void**)&wx,  g_wx16);
    cudaGetSymbolAddress((void**)&wout,g_wout16);
    cudaGetSymbolAddress((void**)&wfg, g_wfg16);
    cudaGetSymbolAddress((void**)&wfu, g_wfu16);
    cudaGetSymbolAddress((void**)&wfd, g_wfd16);

    const int SMEM = STAGES * ASTG * 4 * 2;   // 81920 bytes

    cudaFuncSetAttribute((const void*)gemm_h<EP_NONE>,     cudaFuncAttributeMaxDynamicSharedMemorySize, SMEM);
    cudaFuncSetAttribute((const void*)gemm_h<EP_GATEMUL>,  cudaFuncAttributeMaxDynamicSharedMemorySize, SMEM);
    cudaFuncSetAttribute((const void*)gemm_h<EP_SOFTPLUS>, cudaFuncAttributeMaxDynamicSharedMemorySize, SMEM);
    cudaFuncSetAttribute((const void*)gemm_h<EP_SILUMUL>,  cudaFuncAttributeMaxDynamicSharedMemorySize, SMEM);

    const dim3 blk256(256);

    // 0. Convert all weights to fp16 in one launch
    {
        CvtJobs jobs;
        const float* srcs[8] = {in_proj_w, gate_proj_w, dt_w, x_proj_w,
                                out_proj_w, ffn_gate_w, ffn_up_w, ffn_down_w};
        __half* dsts[8] = {win, wgt, wdt, wx, wout, wfg, wfu, wfd};
        const int ns[8] = {DIN*DM, DIN*DM, DIN*DIN, 2*NST*DIN,
                           DM*DIN, FH*DM, FH*DM, DM*FH};
        int cum = 0;
        for (int j = 0; j < 8; j++) {
            jobs.src[j] = (const float4*)srcs[j];
            jobs.dst[j] = (__half2*)dsts[j];
            jobs.cum[j] = cum;
            cum += ns[j] / 4;
        }
        jobs.cum[8] = cum;
        cvt_all_kernel<<<(cum + 255) / 256, blk256>>>(jobs);
    }

    // 1. h16 = fp16(rmsnorm(x))
    rmsnorm16_kernel<<<ROWS, blk256>>>(x, norm1_w, h16);

    // 2. a = h @ in_proj^T ; z = a * sigmoid(h @ gate_proj^T) -> a (fp32) + a16
    gemm_h<EP_NONE>   <<<dim3(DIN/128, ROWS/128), blk256, SMEM>>>(h16, win, nullptr, nullptr, a,  nullptr, ROWS, DIN, DM, 0, DM, DM, nullptr, nullptr, nullptr);
    gemm_h<EP_GATEMUL><<<dim3(DIN/128, ROWS/128), blk256, SMEM>>>(h16, wgt, a,       nullptr, a,  a16,     ROWS, DIN, DM, 0, DM, DM, nullptr, nullptr, nullptr);

    // 3. dt = softplus(z @ dt_w^T + dt_b)  [+ folded BC = z @ x_proj^T]
    gemm_h<EP_SOFTPLUS><<<dim3(DIN/128 + 1, ROWS/128), blk256, SMEM>>>(a16, wdt, nullptr, dt_b, bb, nullptr, ROWS, DIN, DIN, 0, DIN, DIN, wx, bc, nullptr);

    // 4. scan -> y16
    scan_kernel<<<(BATCH * DIN) / 16, blk256>>>(A_log, Dp);

    // 5. p0/p1 = y @ out_proj^T (K-split); x2 = x + p0 + p1 ; h16 = fp16(rmsnorm(x2))
    gemm_h<EP_NONE><<<dim3(DM/128, ROWS/128, 2), blk256, SMEM>>>(y16, wout, nullptr, nullptr, p0, nullptr, ROWS, DM, DIN/2, DIN/2, DIN, DIN, nullptr, nullptr, p1);
    combine_norm_kernel<<<ROWS, blk256>>>(x, ffn_norm_w, x2, h16);

    // 6. FFN: gg = hn @ Wg^T ; g16 = fp16(silu(gg) * (hn @ Wu^T))
    gemm_h<EP_NONE>   <<<dim3((FH+127)/128, ROWS/128), blk256, SMEM>>>(h16, wfg, nullptr, nullptr, gg, nullptr, ROWS, FH, DM, 0, DM, DM, nullptr, nullptr, nullptr);
    gemm_h<EP_SILUMUL><<<dim3((FH+127)/128, ROWS/128), blk256, SMEM>>>(h16, wfu, gg,      nullptr, nullptr, g16, ROWS, FH, DM, 0, DM, DM, nullptr, nullptr, nullptr);

    // 7. p0/p1 = g16 @ Wd^T (uneven K-split 1408/1344); out = x2 + p0 + p1
    gemm_h<EP_NONE><<<dim3(DM/128, ROWS/128, 2), blk256, SMEM>>>(g16, wfd, nullptr, nullptr, p0, nullptr, ROWS, DM, 1408, 1344, FH, FH, nullptr, nullptr, p1);
    combine_add_kernel<<<(ROWS * DM) / 1024, blk256>>>(x2, out);
}

// round 14
// speedup vs baseline: 1.0695x; 1.0054x over previous
#include <cuda_runtime.h>
#include <cuda_fp16.h>
#include <math.h>
#include <stdint.h>

// Problem dims
constexpr int BATCH = 2;
constexpr int SEQ   = 1024;
constexpr int DM    = 1024;
constexpr int DIN   = 2048;
constexpr int NST   = 16;
constexpr int FH    = 2752;
constexpr int ROWS  = BATCH * SEQ;  // 2048

// fp32 scratch
__device__ float g_a [ROWS * DIN];
__device__ float g_b [ROWS * DIN];
__device__ float g_x2[ROWS * DM];
__device__ float g_bc[ROWS * 2 * NST];
__device__ float g_g [ROWS * FH];
__device__ float g_p0[ROWS * DM];
__device__ float g_p1[ROWS * DM];
// fp16 activations
__device__ __half g_h16[ROWS * DM];
__device__ __half g_a16[ROWS * DIN];
__device__ __half g_y16[ROWS * DIN];
__device__ __half g_g16[ROWS * FH];
// fp16 weights
__device__ __half g_win16 [DIN * DM];
__device__ __half g_wgt16 [DIN * DM];
__device__ __half g_wdt16 [DIN * DIN];
__device__ __half g_wx16  [2 * NST * DIN];
__device__ __half g_wout16[DM * DIN];
__device__ __half g_wfg16 [FH * DM];
__device__ __half g_wfu16 [FH * DM];
__device__ __half g_wfd16 [DM * FH];

constexpr int SW   = 36;             // smem row stride in 4-byte words (64 halfs + pad)
constexpr int ASTG = 128 * SW;       // words per stage per matrix
constexpr int STAGES = 3;

__device__ __forceinline__ uint32_t s2u(const void* p) {
    uint32_t a;
    asm("{ .reg .u64 t; cvta.to.shared.u64 t, %1; cvt.u32.u64 %0, t; }" : "=r"(a) : "l"(p));
    return a;
}
__device__ __forceinline__ void cpa16(uint32_t dst, const __half* src, int szbytes) {
    asm volatile("cp.async.cg.shared.global [%0], [%1], 16, %2;"
                 :: "r"(dst), "l"(src), "r"(szbytes));
}
#define CP_COMMIT() asm volatile("cp.async.commit_group;" ::: "memory")
#define CP_WAIT1()  asm volatile("cp.async.wait_group 1;" ::: "memory")

__device__ __forceinline__ void mma_f16(float c[4],
                                        uint32_t a0, uint32_t a1, uint32_t a2, uint32_t a3,
                                        uint32_t b0, uint32_t b1) {
    asm volatile(
        "mma.sync.aligned.m16n8k16.row.col.f32.f16.f16.f32 "
        "{%0,%1,%2,%3}, {%4,%5,%6,%7}, {%8,%9}, {%0,%1,%2,%3};"
        : "+f"(c[0]), "+f"(c[1]), "+f"(c[2]), "+f"(c[3])
        : "r"(a0), "r"(a1), "r"(a2), "r"(a3), "r"(b0), "r"(b1));
}
#define LDSM4(r0, r1, r2, r3, addr) \
    asm volatile("ldmatrix.sync.aligned.m8n8.x4.shared.b16 {%0,%1,%2,%3}, [%4];" \
        : "=r"(r0), "=r"(r1), "=r"(r2), "=r"(r3) : "r"(addr))

enum { EP_NONE = 0, EP_GATEMUL, EP_SOFTPLUS, EP_SILUMUL };

__device__ __forceinline__ float sigm(float x) { return 1.0f / (1.0f + expf(-x)); }
__device__ __forceinline__ float sftp(float x) { return (x > 20.0f) ? x : log1pf(expf(x)); }

// ---------------------------------------------------------------------------
// fp16 GEMM: ldmatrix + R11 macro shape.
// BM=BN=128, BK=64, 128 threads (4 warps 2x2), warp tile 64x64 (MT=4, NT=8),
// m16n8k16, 3-stage cp.async (110.6KB smem/CTA, 2 CTA/SM).
// K-split: P1 != nullptr -> blockIdx.z=1 reads at column offset K, extent K2.
// Folded side-block (last bx, W2 != nullptr): C2 = A@W2^T, N2=32.
// ---------------------------------------------------------------------------
template<int EP>
__global__ void __launch_bounds__(128, 2) gemm_h(
    const __half* __restrict__ A, const __half* __restrict__ W,
    const float* __restrict__ R, const float* __restrict__ bias,
    float* __restrict__ C, __half* __restrict__ C16,
    int M, int N, int K, int K2, int lda, int ldw,
    const __half* __restrict__ W2, float* __restrict__ C2,
    float* __restrict__ P1)
{
    constexpr int MT = 4, NT = 8;
    extern __shared__ uint32_t sm[];
    uint32_t* As = sm;
    uint32_t* Bs = sm + STAGES * ASTG;
    const uint32_t sbA = s2u(As), sbB = s2u(Bs);

    const int tid  = threadIdx.x;
    const int wid  = tid >> 5, lane = tid & 31;
    const int wm   = wid >> 1, wn = wid & 1;
    const int bm   = blockIdx.y << 7;
    const int bx   = blockIdx.x;
    const int bz   = blockIdx.z;
    const int koff = bz * K;
    const int Kext = bz ? K2 : K;
    float* Cw      = (P1 != nullptr && bz == 1) ? P1 : C;
    const bool isbc = (W2 != nullptr) && (bx == (int)gridDim.x - 1);
    const int bn   = isbc ? 0 : (bx << 7);
    const int Nw   = isbc ? 32 : N;
    const __half* Wk = isbc ? W2 : W;
    const int lr   = lane >> 2, lc = lane & 3;

    float acc[MT][NT][4];
    #pragma unroll
    for (int i = 0; i < MT; i++)
        #pragma unroll
        for (int j = 0; j < NT; j++)
            #pragma unroll
            for (int q = 0; q < 4; q++) acc[i][j][q] = 0.0f;

    // Global->smem: 128 threads, stage = 128 rows x 64 halfs; 8 chunks of 16B
    // per thread per matrix.
    const int row0 = tid >> 3;                // 0..15, +16 per j
    const int ch   = tid & 7;
    const int kh   = ch << 3;
    const int NS   = Kext >> 6;               // BK = 64

    const __half* abase = A  + (size_t)(bm + row0) * lda + koff + kh;
    const int     brow  = bn + row0;
    const uint32_t adst0 = sbA + (uint32_t)((row0 * SW + ch * 4) << 2);
    const uint32_t bdst0 = sbB + (uint32_t)((row0 * SW + ch * 4) << 2);
    constexpr uint32_t STGB = ASTG * 4;
    constexpr uint32_t ROWB = 16 * SW * 4;
    const size_t lda16 = (size_t)lda * 16;

    const __half* bbase[8];
    int bval[8];
    #pragma unroll
    for (int j = 0; j < 8; j++) {
        const int r = brow + 16 * j;
        bval[j]  = (r < Nw) ? 16 : 0;
        bbase[j] = Wk + (size_t)min(r, Nw - 1) * ldw + koff + kh;
    }

    auto issue = [&](int st, int k0) {
        const uint32_t da = adst0 + st * STGB;
        const uint32_t db = bdst0 + st * STGB;
        #pragma unroll
        for (int j = 0; j < 8; j++) cpa16(da + j * ROWB, abase + j * lda16 + k0, 16);
        #pragma unroll
        for (int j = 0; j < 8; j++) cpa16(db + j * ROWB, bbase[j] + k0, bval[j]);
        CP_COMMIT();
    };

    issue(0, 0);
    issue(1, 64);

    // ldmatrix per-lane base offsets (bytes)
    const int arow = lane & 15;
    const int acol = (lane >> 4) << 2;                 // word offset of 16B chunk
    const uint32_t aoff = (uint32_t)(((wm * 64 + arow) * SW + acol) << 2);
    const int brw  = (lane & 7) + ((lane >> 4) << 3);
    const int bcl  = ((lane >> 3) & 1) << 2;
    const uint32_t boff = (uint32_t)(((wn * 64 + brw) * SW + bcl) << 2);
    constexpr uint32_t TMSTR = 16 * SW * 4;            // 16-row stride (bytes)

    int buf = 0;
    for (int ks = 0; ks < NS; ks++) {
        CP_WAIT1();
        __syncthreads();

        if (ks + 2 < NS) {
            int nb = buf + 2; if (nb >= 3) nb -= 3;
            issue(nb, (ks + 2) << 6);
        } else CP_COMMIT();

        const uint32_t Abase = sbA + buf * STGB + aoff;
        const uint32_t Bbase = sbB + buf * STGB + boff;

        #pragma unroll
        for (int kc = 0; kc < 4; kc++) {       // four k16 steps per BK=64
            uint32_t af[MT][4], bf[NT][2];
            #pragma unroll
            for (int tm = 0; tm < MT; tm++)
                LDSM4(af[tm][0], af[tm][1], af[tm][2], af[tm][3],
                      Abase + tm * TMSTR + kc * 32);
            #pragma unroll
            for (int tp = 0; tp < 4; tp++)
                LDSM4(bf[2*tp][0], bf[2*tp][1], bf[2*tp+1][0], bf[2*tp+1][1],
                      Bbase + tp * TMSTR + kc * 32);
            #pragma unroll
            for (int tm = 0; tm < MT; tm++)
                #pragma unroll
                for (int tn = 0; tn < NT; tn++)
                    mma_f16(acc[tm][tn], af[tm][0], af[tm][1], af[tm][2], af[tm][3],
                            bf[tn][0], bf[tn][1]);
        }
        if (++buf == 3) buf = 0;
    }

    if (isbc) {
        #pragma unroll
        for (int tm = 0; tm < MT; tm++) {
            const int row = bm + wm * 64 + tm * 16 + lr;
            #pragma unroll
            for (int tn = 0; tn < NT; tn++) {
                const int col = wn * 64 + tn * 8 + lc * 2;
                if (col < 32) {
                    *(float2*)(C2 + (size_t)row * 32 + col) =
                        make_float2(acc[tm][tn][0], acc[tm][tn][1]);
                    *(float2*)(C2 + (size_t)(row + 8) * 32 + col) =
                        make_float2(acc[tm][tn][2], acc[tm][tn][3]);
                }
            }
        }
        return;
    }

    #pragma unroll
    for (int tm = 0; tm < MT; tm++) {
        const int row = bm + wm * 64 + tm * 16 + lr;
        #pragma unroll
        for (int tn = 0; tn < NT; tn++) {
            const int col = bn + wn * 64 + tn * 8 + lc * 2;
            if (col < N) {
                #pragma unroll
                for (int hf = 0; hf < 2; hf++) {
                    const size_t o = (size_t)(row + hf * 8) * N + col;
                    float v0 = acc[tm][tn][hf * 2], v1 = acc[tm][tn][hf * 2 + 1];
                    if (EP == EP_NONE) {
                        *(float2*)(Cw + o) = make_float2(v0, v1);
                    } else if (EP == EP_GATEMUL) {
                        const float2 r = *(const float2*)(R + o);
                        v0 = r.x * sigm(v0); v1 = r.y * sigm(v1);
                        *(float2*)(C + o) = make_float2(v0, v1);
                        *(__half2*)(C16 + o) = __floats2half2_rn(v0, v1);
                    } else if (EP == EP_SOFTPLUS) {
                        const float2 bv2 = *(const float2*)(bias + col);
                        *(float2*)(C + o) = make_float2(sftp(v0 + bv2.x), sftp(v1 + bv2.y));
                    } else if (EP == EP_SILUMUL) {
                        const float2 r = *(const float2*)(R + o);
                        v0 = r.x * sigm(r.x) * v0; v1 = r.y * sigm(r.y) * v1;
                        *(__half2*)(C16 + o) = __floats2half2_rn(v0, v1);
                    }
                }
            }
        }
    }
}

// ---------------------------------------------------------------------------
// Fused fp32->fp16 conversion of all 8 weight matrices in one launch.
// ---------------------------------------------------------------------------
struct CvtJobs {
    const float4* src[8];
    __half2* dst[8];
    int cum[9];
};

__global__ void __launch_bounds__(256) cvt_all_kernel(CvtJobs jobs)
{
    int i = blockIdx.x * 256 + threadIdx.x;
    if (i >= jobs.cum[8]) return;
    int j = 0;
    #pragma unroll
    for (int t = 1; t < 8; t++) j += (i >= jobs.cum[t]);
    const int li = i - jobs.cum[j];
    const float4 v = jobs.src[j][li];
    jobs.dst[j][2 * li]     = __floats2half2_rn(v.x, v.y);
    jobs.dst[j][2 * li + 1] = __floats2half2_rn(v.z, v.w);
}

// ---------------------------------------------------------------------------
// RMSNorm -> fp16 output
// ---------------------------------------------------------------------------
__global__ void __launch_bounds__(256) rmsnorm16_kernel(
    const float* __restrict__ x, const float* __restrict__ w, __half* __restrict__ out)
{
    __shared__ float red[8];
    const int row = blockIdx.x;
    const int tid = threadIdx.x;
    const float4 v = ((const float4*)(x + (size_t)row * DM))[tid];
    float s = v.x*v.x + v.y*v.y + v.z*v.z + v.w*v.w;
    #pragma unroll
    for (int o = 16; o; o >>= 1) s += __shfl_xor_sync(0xffffffffu, s, o);
    if ((tid & 31) == 0) red[tid >> 5] = s;
    __syncthreads();
    if (tid < 8) {
        float t = red[tid];
        #pragma unroll
        for (int o = 4; o; o >>= 1) t += __shfl_xor_sync(0xffu, t, o);
        if (tid == 0) red[0] = t;
    }
    __syncthreads();
    const float scale = rsqrtf(red[0] * (1.0f / DM) + 1e-6f);
    const float4 wv = ((const float4*)w)[tid];
    __half2* op = (__half2*)(out + (size_t)row * DM) + tid * 2;
    op[0] = __floats2half2_rn(v.x * scale * wv.x, v.y * scale * wv.y);
    op[1] = __floats2half2_rn(v.z * scale * wv.z, v.w * scale * wv.w);
}

// ---------------------------------------------------------------------------
// x2 = x + p0 + p1 ; h16 = fp16(rmsnorm(x2, w))
// ---------------------------------------------------------------------------
__global__ void __launch_bounds__(256) combine_norm_kernel(
    const float* __restrict__ x, const float* __restrict__ w,
    float* __restrict__ x2, __half* __restrict__ h16)
{
    __shared__ float red[8];
    const int row = blockIdx.x;
    const int tid = threadIdx.x;
    const size_t o = (size_t)row * DM / 4 + tid;
    const float4 xv = ((const float4*)x)[o];
    const float4 p0 = ((const float4*)g_p0)[o];
    const float4 p1 = ((const float4*)g_p1)[o];
    float4 v;
    v.x = xv.x + p0.x + p1.x; v.y = xv.y + p0.y + p1.y;
    v.z = xv.z + p0.z + p1.z; v.w = xv.w + p0.w + p1.w;
    ((float4*)x2)[o] = v;
    float s = v.x*v.x + v.y*v.y + v.z*v.z + v.w*v.w;
    #pragma unroll
    for (int of = 16; of; of >>= 1) s += __shfl_xor_sync(0xffffffffu, s, of);
    if ((tid & 31) == 0) red[tid >> 5] = s;
    __syncthreads();
    if (tid < 8) {
        float t = red[tid];
        #pragma unroll
        for (int of = 4; of; of >>= 1) t += __shfl_xor_sync(0xffu, t, of);
        if (tid == 0) red[0] = t;
    }
    __syncthreads();
    const float scale = rsqrtf(red[0] * (1.0f / DM) + 1e-6f);
    const float4 wv = ((const float4*)w)[tid];
    __half2* op = (__half2*)(h16 + (size_t)row * DM) + tid * 2;
    op[0] = __floats2half2_rn(v.x * scale * wv.x, v.y * scale * wv.y);
    op[1] = __floats2half2_rn(v.z * scale * wv.z, v.w * scale * wv.w);
}

// out = x2 + p0 + p1
__global__ void __launch_bounds__(256) combine_add_kernel(
    const float* __restrict__ x2, float* __restrict__ out)
{
    const size_t i = (size_t)blockIdx.x * 256 + threadIdx.x;
    const float4 a = ((const float4*)x2)[i];
    const float4 p0 = ((const float4*)g_p0)[i];
    const float4 p1 = ((const float4*)g_p1)[i];
    float4 v;
    v.x = a.x + p0.x + p1.x; v.y = a.y + p0.y + p1.y;
    v.z = a.z + p0.z + p1.z; v.w = a.w + p0.w + p1.w;
    ((float4*)out)[i] = v;
}

// ---------------------------------------------------------------------------
// Selective scan (16 lanes per channel) -> y16 fp16
// ---------------------------------------------------------------------------
__global__ void __launch_bounds__(256) scan_kernel(
    const float* __restrict__ A_log, const float* __restrict__ Dp)
{
    const int tid = threadIdx.x;
    const int ch  = blockIdx.x * 16 + (tid >> 4);
    const int n   = tid & 15;
    const int b   = ch / DIN;
    const int e   = ch % DIN;

    const float An  = -__expf(A_log[(size_t)e * NST + n]);
    const float dpe = Dp[e];

    const float* dtp = g_b  + (size_t)b * SEQ * DIN + e;
    const float* zp  = g_a  + (size_t)b * SEQ * DIN + e;
    const float* bcp = g_bc + (size_t)b * SEQ * 32;
    __half*      yp  = g_y16 + (size_t)b * SEQ * DIN + e;

    float state = 0.0f;
    #pragma unroll 4
    for (int t = 0; t < SEQ; t++) {
        const float dtv = __ldg(dtp + (size_t)t * DIN);
        const float zv  = __ldg(zp  + (size_t)t * DIN);
        const float Bn  = bcp[t * 32 + n];
        const float Cn  = bcp[t * 32 + 16 + n];
        state = __expf(dtv * An) * state + dtv * zv * Bn;
        float s = state * Cn;
        s += __shfl_xor_sync(0xffffffffu, s, 8);
        s += __shfl_xor_sync(0xffffffffu, s, 4);
        s += __shfl_xor_sync(0xffffffffu, s, 2);
        s += __shfl_xor_sync(0xffffffffu, s, 1);
        if (n == 0) yp[(size_t)t * DIN] = __float2half_rn(s + zv * dpe);
    }
}

// ---------------------------------------------------------------------------
// Launch
// ---------------------------------------------------------------------------
extern "C" void kernel_launch(void* const* d_in, const int* in_sizes, int n_in,
                              void* d_out, int out_size)
{
    const float* x          = (const float*)d_in[0];
    const float* norm1_w    = (const float*)d_in[1];
    const float* in_proj_w  = (const float*)d_in[2];
    const float* gate_proj_w= (const float*)d_in[3];
    const float* dt_w       = (const float*)d_in[4];
    const float* dt_b       = (const float*)d_in[5];
    const float* x_proj_w   = (const float*)d_in[6];
    const float* A_log      = (const float*)d_in[7];
    const float* Dp         = (const float*)d_in[8];
    const float* out_proj_w = (const float*)d_in[9];
    const float* ffn_norm_w = (const float*)d_in[10];
    const float* ffn_gate_w = (const float*)d_in[11];
    const float* ffn_up_w   = (const float*)d_in[12];
    const float* ffn_down_w = (const float*)d_in[13];
    float* out = (float*)d_out;

    float *a, *bb, *x2, *gg, *bc, *p0, *p1;
    __half *h16, *a16, *y16, *g16;
    __half *win, *wgt, *wdt, *wx, *wout, *wfg, *wfu, *wfd;
    cudaGetSymbolAddress((void**)&a,   g_a);
    cudaGetSymbolAddress((void**)&bb,  g_b);
    cudaGetSymbolAddress((void**)&x2,  g_x2);
    cudaGetSymbolAddress((void**)&gg,  g_g);
    cudaGetSymbolAddress((void**)&bc,  g_bc);
    cudaGetSymbolAddress((void**)&p0,  g_p0);
    cudaGetSymbolAddress((void**)&p1,  g_p1);
    cudaGetSymbolAddress((void**)&h16, g_h16);
    cudaGetSymbolAddress((void**)&a16, g_a16);
    cudaGetSymbolAddress((void**)&y16, g_y16);
    cudaGetSymbolAddress((void**)&g16, g_g16);
    cudaGetSymbolAddress((void**)&win, g_win16);
    cudaGetSymbolAddress((void**)&wgt, g_wgt16);
    cudaGetSymbolAddress((void**)&wdt, g_wdt16);
    cudaGetSymbolAddress((void**)&wx,  g_wx16);
    cudaGetSymbolAddress((void**)&wout,g_wout16);
    cudaGetSymbolAddress((void**)&wfg, g_wfg16);
    cudaGetSymbolAddress((void**)&wfu, g_wfu16);
    cudaGetSymbolAddress((void**)&wfd, g_wfd16);

    const int SMEM = STAGES * ASTG * 4 * 2;   // 110592 bytes

    cudaFuncSetAttribute((const void*)gemm_h<EP_NONE>,     cudaFuncAttributeMaxDynamicSharedMemorySize, SMEM);
    cudaFuncSetAttribute((const void*)gemm_h<EP_GATEMUL>,  cudaFuncAttributeMaxDynamicSharedMemorySize, SMEM);
    cudaFuncSetAttribute((const void*)gemm_h<EP_SOFTPLUS>, cudaFuncAttributeMaxDynamicSharedMemorySize, SMEM);
    cudaFuncSetAttribute((const void*)gemm_h<EP_SILUMUL>,  cudaFuncAttributeMaxDynamicSharedMemorySize, SMEM);

    const dim3 blk256(256), blk128(128);

    // 0. Convert all weights to fp16 in one launch
    {
        CvtJobs jobs;
        const float* srcs[8] = {in_proj_w, gate_proj_w, dt_w, x_proj_w,
                                out_proj_w, ffn_gate_w, ffn_up_w, ffn_down_w};
        __half* dsts[8] = {win, wgt, wdt, wx, wout, wfg, wfu, wfd};
        const int ns[8] = {DIN*DM, DIN*DM, DIN*DIN, 2*NST*DIN,
                           DM*DIN, FH*DM, FH*DM, DM*FH};
        int cum = 0;
        for (int j = 0; j < 8; j++) {
            jobs.src[j] = (const float4*)srcs[j];
            jobs.dst[j] = (__half2*)dsts[j];
            jobs.cum[j] = cum;
            cum += ns[j] / 4;
        }
        jobs.cum[8] = cum;
        cvt_all_kernel<<<(cum + 255) / 256, blk256>>>(jobs);
    }

    // 1. h16 = fp16(rmsnorm(x))
    rmsnorm16_kernel<<<ROWS, blk256>>>(x, norm1_w, h16);

    // 2. a = h @ in_proj^T ; z = a * sigmoid(h @ gate_proj^T) -> a (fp32) + a16
    gemm_h<EP_NONE>   <<<dim3(DIN/128, ROWS/128), blk128, SMEM>>>(h16, win, nullptr, nullptr, a,  nullptr, ROWS, DIN, DM, 0, DM, DM, nullptr, nullptr, nullptr);
    gemm_h<EP_GATEMUL><<<dim3(DIN/128, ROWS/128), blk128, SMEM>>>(h16, wgt, a,       nullptr, a,  a16,     ROWS, DIN, DM, 0, DM, DM, nullptr, nullptr, nullptr);

    // 3. dt = softplus(z @ dt_w^T + dt_b)  [+ folded BC = z @ x_proj^T]
    gemm_h<EP_SOFTPLUS><<<dim3(DIN/128 + 1, ROWS/128), blk128, SMEM>>>(a16, wdt, nullptr, dt_b, bb, nullptr, ROWS, DIN, DIN, 0, DIN, DIN, wx, bc, nullptr);

    // 4. scan -> y16
    scan_kernel<<<(BATCH * DIN) / 16, blk256>>>(A_log, Dp);

    // 5. p0/p1 = y @ out_proj^T (K-split); x2 = x + p0 + p1 ; h16 = fp16(rmsnorm(x2))
    gemm_h<EP_NONE><<<dim3(DM/128, ROWS/128, 2), blk128, SMEM>>>(y16, wout, nullptr, nullptr, p0, nullptr, ROWS, DM, DIN/2, DIN/2, DIN, DIN, nullptr, nullptr, p1);
    combine_norm_kernel<<<ROWS, blk256>>>(x, ffn_norm_w, x2, h16);

    // 6. FFN: gg = hn @ Wg^T ; g16 = fp16(silu(gg) * (hn @ Wu^T))
    gemm_h<EP_NONE>   <<<dim3((FH+127)/128, ROWS/128), blk128, SMEM>>>(h16, wfg, nullptr, nullptr, gg, nullptr, ROWS, FH, DM, 0, DM, DM, nullptr, nullptr, nullptr);
    gemm_h<EP_SILUMUL><<<dim3((FH+127)/128, ROWS/128), blk128, SMEM>>>(h16, wfu, gg,      nullptr, nullptr, g16, ROWS, FH, DM, 0, DM, DM, nullptr, nullptr, nullptr);

    // 7. p0/p1 = g16 @ Wd^T (uneven K-split 1408/1344); out = x2 + p0 + p1
    gemm_h<EP_NONE><<<dim3(DM/128, ROWS/128, 2), blk128, SMEM>>>(g16, wfd, nullptr, nullptr, p0, nullptr, ROWS, DM, 1408, 1344, FH, FH, nullptr, nullptr, p1);
    combine_add_kernel<<<(ROWS * DM) / 1024, blk256>>>(x2, out);
}

// round 15
// speedup vs baseline: 1.1977x; 1.1199x over previous
#include <cuda_runtime.h>
#include <cuda_fp16.h>
#include <math.h>
#include <stdint.h>

// Problem dims
constexpr int BATCH = 2;
constexpr int SEQ   = 1024;
constexpr int DM    = 1024;
constexpr int DIN   = 2048;
constexpr int NST   = 16;
constexpr int FH    = 2752;
constexpr int ROWS  = BATCH * SEQ;  // 2048

// fp32 scratch
__device__ float g_a [ROWS * DIN];
__device__ float g_b [ROWS * DIN];
__device__ float g_x2[ROWS * DM];
__device__ float g_bc[ROWS * 2 * NST];
__device__ float g_g [ROWS * FH];
__device__ float g_p0[ROWS * DM];
__device__ float g_p1[ROWS * DM];
// fp16 activations
__device__ __half g_h16[ROWS * DM];
__device__ __half g_a16[ROWS * DIN];
__device__ __half g_y16[ROWS * DIN];
__device__ __half g_g16[ROWS * FH];
// fp16 weights
__device__ __half g_win16 [DIN * DM];
__device__ __half g_wgt16 [DIN * DM];
__device__ __half g_wdt16 [DIN * DIN];
__device__ __half g_wx16  [2 * NST * DIN];
__device__ __half g_wout16[DM * DIN];
__device__ __half g_wfg16 [FH * DM];
__device__ __half g_wfu16 [FH * DM];
__device__ __half g_wfd16 [DM * FH];

constexpr int SW   = 36;             // smem row stride in 4-byte words (64 halfs + pad)
constexpr int ASTG = 128 * SW;       // words per stage per matrix
constexpr int STAGES = 3;

__device__ __forceinline__ uint32_t s2u(const void* p) {
    uint32_t a;
    asm("{ .reg .u64 t; cvta.to.shared.u64 t, %1; cvt.u32.u64 %0, t; }" : "=r"(a) : "l"(p));
    return a;
}
__device__ __forceinline__ void cpa16(uint32_t dst, const __half* src, int szbytes) {
    asm volatile("cp.async.cg.shared.global [%0], [%1], 16, %2;"
                 :: "r"(dst), "l"(src), "r"(szbytes));
}
#define CP_COMMIT() asm volatile("cp.async.commit_group;" ::: "memory")
#define CP_WAIT1()  asm volatile("cp.async.wait_group 1;" ::: "memory")

__device__ __forceinline__ void mma_f16(float c[4],
                                        uint32_t a0, uint32_t a1, uint32_t a2, uint32_t a3,
                                        uint32_t b0, uint32_t b1) {
    asm volatile(
        "mma.sync.aligned.m16n8k16.row.col.f32.f16.f16.f32 "
        "{%0,%1,%2,%3}, {%4,%5,%6,%7}, {%8,%9}, {%0,%1,%2,%3};"
        : "+f"(c[0]), "+f"(c[1]), "+f"(c[2]), "+f"(c[3])
        : "r"(a0), "r"(a1), "r"(a2), "r"(a3), "r"(b0), "r"(b1));
}
#define LDSM4(r0, r1, r2, r3, addr) \
    asm volatile("ldmatrix.sync.aligned.m8n8.x4.shared.b16 {%0,%1,%2,%3}, [%4];" \
        : "=r"(r0), "=r"(r1), "=r"(r2), "=r"(r3) : "r"(addr))

enum { EP_NONE = 0, EP_GATEMUL, EP_SOFTPLUS, EP_SILUMUL };

__device__ __forceinline__ float sigm(float x) { return 1.0f / (1.0f + expf(-x)); }
__device__ __forceinline__ float sftp(float x) { return (x > 20.0f) ? x : log1pf(expf(x)); }

// ---------------------------------------------------------------------------
// fp16 GEMM: ldmatrix + BK=64 + 16 warps/SM.
// BM=BN=128, BK=64, 256 threads (8 warps 2x4), warp tile 64x32 (MT=4, NT=4),
// m16n8k16, 3-stage cp.async (110.6KB smem/CTA), ~126 regs -> 2 CTA/SM.
// K-split: P1 != nullptr -> blockIdx.z=1 reads at column offset K, extent K2.
// Folded side-block (last bx, W2 != nullptr): C2 = A@W2^T, N2=32.
// ---------------------------------------------------------------------------
template<int EP>
__global__ void __launch_bounds__(256, 2) gemm_h(
    const __half* __restrict__ A, const __half* __restrict__ W,
    const float* __restrict__ R, const float* __restrict__ bias,
    float* __restrict__ C, __half* __restrict__ C16,
    int M, int N, int K, int K2, int lda, int ldw,
    const __half* __restrict__ W2, float* __restrict__ C2,
    float* __restrict__ P1)
{
    constexpr int MT = 4, NT = 4;
    extern __shared__ uint32_t sm[];
    uint32_t* As = sm;
    uint32_t* Bs = sm + STAGES * ASTG;
    const uint32_t sbA = s2u(As), sbB = s2u(Bs);

    const int tid  = threadIdx.x;
    const int wid  = tid >> 5, lane = tid & 31;
    const int wm   = wid >> 2, wn = wid & 3;
    const int bm   = blockIdx.y << 7;
    const int bx   = blockIdx.x;
    const int bz   = blockIdx.z;
    const int koff = bz * K;
    const int Kext = bz ? K2 : K;
    float* Cw      = (P1 != nullptr && bz == 1) ? P1 : C;
    const bool isbc = (W2 != nullptr) && (bx == (int)gridDim.x - 1);
    const int bn   = isbc ? 0 : (bx << 7);
    const int Nw   = isbc ? 32 : N;
    const __half* Wk = isbc ? W2 : W;
    const int lr   = lane >> 2, lc = lane & 3;

    float acc[MT][NT][4];
    #pragma unroll
    for (int i = 0; i < MT; i++)
        #pragma unroll
        for (int j = 0; j < NT; j++)
            #pragma unroll
            for (int q = 0; q < 4; q++) acc[i][j][q] = 0.0f;

    // Global->smem: 256 threads, stage = 128 rows x 64 halfs (128B/row);
    // 4 chunks of 16B per thread per matrix.
    const int row0 = tid >> 3;                // 0..31, +32 per j
    const int ch   = tid & 7;
    const int kh   = ch << 3;
    const int NS   = Kext >> 6;               // BK = 64

    const __half* abase = A + (size_t)(bm + row0) * lda + koff + kh;
    const uint32_t adst0 = sbA + (uint32_t)((row0 * SW + ch * 4) << 2);
    const uint32_t bdst0 = sbB + (uint32_t)((row0 * SW + ch * 4) << 2);
    constexpr uint32_t STGB = ASTG * 4;
    constexpr uint32_t ROWB = 32 * SW * 4;    // 32-row stride in bytes
    const size_t lda32 = (size_t)lda * 32;

    const __half* bbase[4];
    int bval[4];
    #pragma unroll
    for (int j = 0; j < 4; j++) {
        const int r = bn + row0 + 32 * j;
        bval[j]  = (r < Nw) ? 16 : 0;
        bbase[j] = Wk + (size_t)min(r, Nw - 1) * ldw + koff + kh;
    }

    auto issue = [&](int st, int k0) {
        const uint32_t da = adst0 + st * STGB;
        const uint32_t db = bdst0 + st * STGB;
        #pragma unroll
        for (int j = 0; j < 4; j++) cpa16(da + j * ROWB, abase + j * lda32 + k0, 16);
        #pragma unroll
        for (int j = 0; j < 4; j++) cpa16(db + j * ROWB, bbase[j] + k0, bval[j]);
        CP_COMMIT();
    };

    issue(0, 0);
    issue(1, 64);

    // ldmatrix per-lane base offsets (bytes)
    const int arow = lane & 15;
    const int acol = (lane >> 4) << 2;                 // word offset of 16B chunk
    const uint32_t aoff = (uint32_t)(((wm * 64 + arow) * SW + acol) << 2);
    const int brw  = (lane & 7) + ((lane >> 4) << 3);
    const int bcl  = ((lane >> 3) & 1) << 2;
    const uint32_t boff = (uint32_t)(((wn * 32 + brw) * SW + bcl) << 2);
    constexpr uint32_t TMSTR = 16 * SW * 4;            // 16-row stride (bytes)

    int buf = 0;
    for (int ks = 0; ks < NS; ks++) {
        CP_WAIT1();
        __syncthreads();

        if (ks + 2 < NS) {
            int nb = buf + 2; if (nb >= 3) nb -= 3;
            issue(nb, (ks + 2) << 6);
        } else CP_COMMIT();

        const uint32_t Abase = sbA + buf * STGB + aoff;
        const uint32_t Bbase = sbB + buf * STGB + boff;

        #pragma unroll
        for (int kc = 0; kc < 4; kc++) {       // four k16 steps per BK=64
            uint32_t af[MT][4], bf[NT][2];
            #pragma unroll
            for (int tm = 0; tm < MT; tm++)
                LDSM4(af[tm][0], af[tm][1], af[tm][2], af[tm][3],
                      Abase + tm * TMSTR + kc * 32);
            #pragma unroll
            for (int tp = 0; tp < 2; tp++)
                LDSM4(bf[2*tp][0], bf[2*tp][1], bf[2*tp+1][0], bf[2*tp+1][1],
                      Bbase + tp * TMSTR + kc * 32);
            #pragma unroll
            for (int tm = 0; tm < MT; tm++)
                #pragma unroll
                for (int tn = 0; tn < NT; tn++)
                    mma_f16(acc[tm][tn], af[tm][0], af[tm][1], af[tm][2], af[tm][3],
                            bf[tn][0], bf[tn][1]);
        }
        if (++buf == 3) buf = 0;
    }

    if (isbc) {
        #pragma unroll
        for (int tm = 0; tm < MT; tm++) {
            const int row = bm + wm * 64 + tm * 16 + lr;
            #pragma unroll
            for (int tn = 0; tn < NT; tn++) {
                const int col = wn * 32 + tn * 8 + lc * 2;
                if (col < 32) {
                    *(float2*)(C2 + (size_t)row * 32 + col) =
                        make_float2(acc[tm][tn][0], acc[tm][tn][1]);
                    *(float2*)(C2 + (size_t)(row + 8) * 32 + col) =
                        make_float2(acc[tm][tn][2], acc[tm][tn][3]);
                }
            }
        }
        return;
    }

    #pragma unroll
    for (int tm = 0; tm < MT; tm++) {
        const int row = bm + wm * 64 + tm * 16 + lr;
        #pragma unroll
        for (int tn = 0; tn < NT; tn++) {
            const int col = bn + wn * 32 + tn * 8 + lc * 2;
            if (col < N) {
                #pragma unroll
                for (int hf = 0; hf < 2; hf++) {
                    const size_t o = (size_t)(row + hf * 8) * N + col;
                    float v0 = acc[tm][tn][hf * 2], v1 = acc[tm][tn][hf * 2 + 1];
                    if (EP == EP_NONE) {
                        *(float2*)(Cw + o) = make_float2(v0, v1);
                    } else if (EP == EP_GATEMUL) {
                        const float2 r = *(const float2*)(R + o);
                        v0 = r.x * sigm(v0); v1 = r.y * sigm(v1);
                        *(float2*)(C + o) = make_float2(v0, v1);
                        *(__half2*)(C16 + o) = __floats2half2_rn(v0, v1);
                    } else if (EP == EP_SOFTPLUS) {
                        const float2 bv2 = *(const float2*)(bias + col);
                        *(float2*)(C + o) = make_float2(sftp(v0 + bv2.x), sftp(v1 + bv2.y));
                    } else if (EP == EP_SILUMUL) {
                        const float2 r = *(const float2*)(R + o);
                        v0 = r.x * sigm(r.x) * v0; v1 = r.y * sigm(r.y) * v1;
                        *(__half2*)(C16 + o) = __floats2half2_rn(v0, v1);
                    }
                }
            }
        }
    }
}

// ---------------------------------------------------------------------------
// Fused fp32->fp16 conversion of all 8 weight matrices in one launch.
// ---------------------------------------------------------------------------
struct CvtJobs {
    const float4* src[8];
    __half2* dst[8];
    int cum[9];
};

__global__ void __launch_bounds__(256) cvt_all_kernel(CvtJobs jobs)
{
    int i = blockIdx.x * 256 + threadIdx.x;
    if (i >= jobs.cum[8]) return;
    int j = 0;
    #pragma unroll
    for (int t = 1; t < 8; t++) j += (i >= jobs.cum[t]);
    const int li = i - jobs.cum[j];
    const float4 v = jobs.src[j][li];
    jobs.dst[j][2 * li]     = __floats2half2_rn(v.x, v.y);
    jobs.dst[j][2 * li + 1] = __floats2half2_rn(v.z, v.w);
}

// ---------------------------------------------------------------------------
// RMSNorm -> fp16 output
// ---------------------------------------------------------------------------
__global__ void __launch_bounds__(256) rmsnorm16_kernel(
    const float* __restrict__ x, const float* __restrict__ w, __half* __restrict__ out)
{
    __shared__ float red[8];
    const int row = blockIdx.x;
    const int tid = threadIdx.x;
    const float4 v = ((const float4*)(x + (size_t)row * DM))[tid];
    float s = v.x*v.x + v.y*v.y + v.z*v.z + v.w*v.w;
    #pragma unroll
    for (int o = 16; o; o >>= 1) s += __shfl_xor_sync(0xffffffffu, s, o);
    if ((tid & 31) == 0) red[tid >> 5] = s;
    __syncthreads();
    if (tid < 8) {
        float t = red[tid];
        #pragma unroll
        for (int o = 4; o; o >>= 1) t += __shfl_xor_sync(0xffu, t, o);
        if (tid == 0) red[0] = t;
    }
    __syncthreads();
    const float scale = rsqrtf(red[0] * (1.0f / DM) + 1e-6f);
    const float4 wv = ((const float4*)w)[tid];
    __half2* op = (__half2*)(out + (size_t)row * DM) + tid * 2;
    op[0] = __floats2half2_rn(v.x * scale * wv.x, v.y * scale * wv.y);
    op[1] = __floats2half2_rn(v.z * scale * wv.z, v.w * scale * wv.w);
}

// ---------------------------------------------------------------------------
// x2 = x + p0 + p1 ; h16 = fp16(rmsnorm(x2, w))
// ---------------------------------------------------------------------------
__global__ void __launch_bounds__(256) combine_norm_kernel(
    const float* __restrict__ x, const float* __restrict__ w,
    float* __restrict__ x2, __half* __restrict__ h16)
{
    __shared__ float red[8];
    const int row = blockIdx.x;
    const int tid = threadIdx.x;
    const size_t o = (size_t)row * DM / 4 + tid;
    const float4 xv = ((const float4*)x)[o];
    const float4 p0 = ((const float4*)g_p0)[o];
    const float4 p1 = ((const float4*)g_p1)[o];
    float4 v;
    v.x = xv.x + p0.x + p1.x; v.y = xv.y + p0.y + p1.y;
    v.z = xv.z + p0.z + p1.z; v.w = xv.w + p0.w + p1.w;
    ((float4*)x2)[o] = v;
    float s = v.x*v.x + v.y*v.y + v.z*v.z + v.w*v.w;
    #pragma unroll
    for (int of = 16; of; of >>= 1) s += __shfl_xor_sync(0xffffffffu, s, of);
    if ((tid & 31) == 0) red[tid >> 5] = s;
    __syncthreads();
    if (tid < 8) {
        float t = red[tid];
        #pragma unroll
        for (int of = 4; of; of >>= 1) t += __shfl_xor_sync(0xffu, t, of);
        if (tid == 0) red[0] = t;
    }
    __syncthreads();
    const float scale = rsqrtf(red[0] * (1.0f / DM) + 1e-6f);
    const float4 wv = ((const float4*)w)[tid];
    __half2* op = (__half2*)(h16 + (size_t)row * DM) + tid * 2;
    op[0] = __floats2half2_rn(v.x * scale * wv.x, v.y * scale * wv.y);
    op[1] = __floats2half2_rn(v.z * scale * wv.z, v.w * scale * wv.w);
}

// out = x2 + p0 + p1
__global__ void __launch_bounds__(256) combine_add_kernel(
    const float* __restrict__ x2, float* __restrict__ out)
{
    const size_t i = (size_t)blockIdx.x * 256 + threadIdx.x;
    const float4 a = ((const float4*)x2)[i];
    const float4 p0 = ((const float4*)g_p0)[i];
    const float4 p1 = ((const float4*)g_p1)[i];
    float4 v;
    v.x = a.x + p0.x + p1.x; v.y = a.y + p0.y + p1.y;
    v.z = a.z + p0.z + p1.z; v.w = a.w + p0.w + p1.w;
    ((float4*)out)[i] = v;
}

// ---------------------------------------------------------------------------
// Selective scan (16 lanes per channel) -> y16 fp16
// ---------------------------------------------------------------------------
__global__ void __launch_bounds__(256) scan_kernel(
    const float* __restrict__ A_log, const float* __restrict__ Dp)
{
    const int tid = threadIdx.x;
    const int ch  = blockIdx.x * 16 + (tid >> 4);
    const int n   = tid & 15;
    const int b   = ch / DIN;
    const int e   = ch % DIN;

    const float An  = -__expf(A_log[(size_t)e * NST + n]);
    const float dpe = Dp[e];

    const float* dtp = g_b  + (size_t)b * SEQ * DIN + e;
    const float* zp  = g_a  + (size_t)b * SEQ * DIN + e;
    const float* bcp = g_bc + (size_t)b * SEQ * 32;
    __half*      yp  = g_y16 + (size_t)b * SEQ * DIN + e;

    float state = 0.0f;
    #pragma unroll 4
    for (int t = 0; t < SEQ; t++) {
        const float dtv = __ldg(dtp + (size_t)t * DIN);
        const float zv  = __ldg(zp  + (size_t)t * DIN);
        const float Bn  = bcp[t * 32 + n];
        const float Cn  = bcp[t * 32 + 16 + n];
        state = __expf(dtv * An) * state + dtv * zv * Bn;
        float s = state * Cn;
        s += __shfl_xor_sync(0xffffffffu, s, 8);
        s += __shfl_xor_sync(0xffffffffu, s, 4);
        s += __shfl_xor_sync(0xffffffffu, s, 2);
        s += __shfl_xor_sync(0xffffffffu, s, 1);
        if (n == 0) yp[(size_t)t * DIN] = __float2half_rn(s + zv * dpe);
    }
}

// ---------------------------------------------------------------------------
// Launch
// ---------------------------------------------------------------------------
extern "C" void kernel_launch(void* const* d_in, const int* in_sizes, int n_in,
                              void* d_out, int out_size)
{
    const float* x          = (const float*)d_in[0];
    const float* norm1_w    = (const float*)d_in[1];
    const float* in_proj_w  = (const float*)d_in[2];
    const float* gate_proj_w= (const float*)d_in[3];
    const float* dt_w       = (const float*)d_in[4];
    const float* dt_b       = (const float*)d_in[5];
    const float* x_proj_w   = (const float*)d_in[6];
    const float* A_log      = (const float*)d_in[7];
    const float* Dp         = (const float*)d_in[8];
    const float* out_proj_w = (const float*)d_in[9];
    const float* ffn_norm_w = (const float*)d_in[10];
    const float* ffn_gate_w = (const float*)d_in[11];
    const float* ffn_up_w   = (const float*)d_in[12];
    const float* ffn_down_w = (const float*)d_in[13];
    float* out = (float*)d_out;

    float *a, *bb, *x2, *gg, *bc, *p0, *p1;
    __half *h16, *a16, *y16, *g16;
    __half *win, *wgt, *wdt, *wx, *wout, *wfg, *wfu, *wfd;
    cudaGetSymbolAddress((void**)&a,   g_a);
    cudaGetSymbolAddress((void**)&bb,  g_b);
    cudaGetSymbolAddress((void**)&x2,  g_x2);
    cudaGetSymbolAddress((void**)&gg,  g_g);
    cudaGetSymbolAddress((void**)&bc,  g_bc);
    cudaGetSymbolAddress((void**)&p0,  g_p0);
    cudaGetSymbolAddress((void**)&p1,  g_p1);
    cudaGetSymbolAddress((void**)&h16, g_h16);
    cudaGetSymbolAddress((void**)&a16, g_a16);
    cudaGetSymbolAddress((void**)&y16, g_y16);
    cudaGetSymbolAddress((void**)&g16, g_g16);
    cudaGetSymbolAddress((void**)&win, g_win16);
    cudaGetSymbolAddress((void**)&wgt, g_wgt16);
    cudaGetSymbolAddress((void**)&wdt, g_wdt16);
    cudaGetSymbolAddress((void**)&wx,  g_wx16);
    cudaGetSymbolAddress((void**)&wout,g_wout16);
    cudaGetSymbolAddress((void**)&wfg, g_wfg16);
    cudaGetSymbolAddress((void**)&wfu, g_wfu16);
    cudaGetSymbolAddress((void**)&wfd, g_wfd16);

    const int SMEM = STAGES * ASTG * 4 * 2;   // 110592 bytes

    cudaFuncSetAttribute((const void*)gemm_h<EP_NONE>,     cudaFuncAttributeMaxDynamicSharedMemorySize, SMEM);
    cudaFuncSetAttribute((const void*)gemm_h<EP_GATEMUL>,  cudaFuncAttributeMaxDynamicSharedMemorySize, SMEM);
    cudaFuncSetAttribute((const void*)gemm_h<EP_SOFTPLUS>, cudaFuncAttributeMaxDynamicSharedMemorySize, SMEM);
    cudaFuncSetAttribute((const void*)gemm_h<EP_SILUMUL>,  cudaFuncAttributeMaxDynamicSharedMemorySize, SMEM);

    const dim3 blk256(256);

    // 0. Convert all weights to fp16 in one launch
    {
        CvtJobs jobs;
        const float* srcs[8] = {in_proj_w, gate_proj_w, dt_w, x_proj_w,
                                out_proj_w, ffn_gate_w, ffn_up_w, ffn_down_w};
        __half* dsts[8] = {win, wgt, wdt, wx, wout, wfg, wfu, wfd};
        const int ns[8] = {DIN*DM, DIN*DM, DIN*DIN, 2*NST*DIN,
                           DM*DIN, FH*DM, FH*DM, DM*FH};
        int cum = 0;
        for (int j = 0; j < 8; j++) {
            jobs.src[j] = (const float4*)srcs[j];
            jobs.dst[j] = (__half2*)dsts[j];
            jobs.cum[j] = cum;
            cum += ns[j] / 4;
        }
        jobs.cum[8] = cum;
        cvt_all_kernel<<<(cum + 255) / 256, blk256>>>(jobs);
    }

    // 1. h16 = fp16(rmsnorm(x))
    rmsnorm16_kernel<<<ROWS, blk256>>>(x, norm1_w, h16);

    // 2. a = h @ in_proj^T ; z = a * sigmoid(h @ gate_proj^T) -> a (fp32) + a16
    gemm_h<EP_NONE>   <<<dim3(DIN/128, ROWS/128), blk256, SMEM>>>(h16, win, nullptr, nullptr, a,  nullptr, ROWS, DIN, DM, 0, DM, DM, nullptr, nullptr, nullptr);
    gemm_h<EP_GATEMUL><<<dim3(DIN/128, ROWS/128), blk256, SMEM>>>(h16, wgt, a,       nullptr, a,  a16,     ROWS, DIN, DM, 0, DM, DM, nullptr, nullptr, nullptr);

    // 3. dt = softplus(z @ dt_w^T + dt_b)  [+ folded BC = z @ x_proj^T]
    gemm_h<EP_SOFTPLUS><<<dim3(DIN/128 + 1, ROWS/128), blk256, SMEM>>>(a16, wdt, nullptr, dt_b, bb, nullptr, ROWS, DIN, DIN, 0, DIN, DIN, wx, bc, nullptr);

    // 4. scan -> y16
    scan_kernel<<<(BATCH * DIN) / 16, blk256>>>(A_log, Dp);

    // 5. p0/p1 = y @ out_proj^T (K-split); x2 = x + p0 + p1 ; h16 = fp16(rmsnorm(x2))
    gemm_h<EP_NONE><<<dim3(DM/128, ROWS/128, 2), blk256, SMEM>>>(y16, wout, nullptr, nullptr, p0, nullptr, ROWS, DM, DIN/2, DIN/2, DIN, DIN, nullptr, nullptr, p1);
    combine_norm_kernel<<<ROWS, blk256>>>(x, ffn_norm_w, x2, h16);

    // 6. FFN: gg = hn @ Wg^T ; g16 = fp16(silu(gg) * (hn @ Wu^T))
    gemm_h<EP_NONE>   <<<dim3((FH+127)/128, ROWS/128), blk256, SMEM>>>(h16, wfg, nullptr, nullptr, gg, nullptr, ROWS, FH, DM, 0, DM, DM, nullptr, nullptr, nullptr);
    gemm_h<EP_SILUMUL><<<dim3((FH+127)/128, ROWS/128), blk256, SMEM>>>(h16, wfu, gg,      nullptr, nullptr, g16, ROWS, FH, DM, 0, DM, DM, nullptr, nullptr, nullptr);

    // 7. p0/p1 = g16 @ Wd^T (uneven K-split 1408/1344); out = x2 + p0 + p1
    gemm_h<EP_NONE><<<dim3(DM/128, ROWS/128, 2), blk256, SMEM>>>(g16, wfd, nullptr, nullptr, p0, nullptr, ROWS, DM, 1408, 1344, FH, FH, nullptr, nullptr, p1);
    combine_add_kernel<<<(ROWS * DM) / 1024, blk256>>>(x2, out);
}

// round 16
// speedup vs baseline: 1.2086x; 1.0091x over previous
#include <cuda_runtime.h>
#include <cuda_fp16.h>
#include <math.h>
#include <stdint.h>

// Problem dims
constexpr int BATCH = 2;
constexpr int SEQ   = 1024;
constexpr int DM    = 1024;
constexpr int DIN   = 2048;
constexpr int NST   = 16;
constexpr int FH    = 2752;
constexpr int ROWS  = BATCH * SEQ;  // 2048

// fp32 scratch
__device__ float g_a [ROWS * DIN];
__device__ float g_b [ROWS * DIN];
__device__ float g_x2[ROWS * DM];
__device__ float g_bc[ROWS * 2 * NST];
__device__ float g_g [ROWS * FH];     // raw gemm output 1 (in-proj / ffn-gate)
__device__ float g_u [ROWS * FH];     // raw gemm output 2 (gate-proj / ffn-up)
__device__ float g_p0[ROWS * DM];
__device__ float g_p1[ROWS * DM];
// fp16 activations
__device__ __half g_h16[ROWS * DM];
__device__ __half g_a16[ROWS * DIN];
__device__ __half g_y16[ROWS * DIN];
__device__ __half g_g16[ROWS * FH];
// fp16 weights
__device__ __half g_win16 [DIN * DM];
__device__ __half g_wgt16 [DIN * DM];
__device__ __half g_wdt16 [DIN * DIN];
__device__ __half g_wx16  [2 * NST * DIN];
__device__ __half g_wout16[DM * DIN];
__device__ __half g_wfg16 [FH * DM];
__device__ __half g_wfu16 [FH * DM];
__device__ __half g_wfd16 [DM * FH];

constexpr int SW   = 36;             // smem row stride in 4-byte words
constexpr int ASTG = 128 * SW;
constexpr int STAGES = 3;

__device__ __forceinline__ uint32_t s2u(const void* p) {
    uint32_t a;
    asm("{ .reg .u64 t; cvta.to.shared.u64 t, %1; cvt.u32.u64 %0, t; }" : "=r"(a) : "l"(p));
    return a;
}
__device__ __forceinline__ void cpa16(uint32_t dst, const __half* src, int szbytes) {
    asm volatile("cp.async.cg.shared.global [%0], [%1], 16, %2;"
                 :: "r"(dst), "l"(src), "r"(szbytes));
}
#define CP_COMMIT() asm volatile("cp.async.commit_group;" ::: "memory")
#define CP_WAIT1()  asm volatile("cp.async.wait_group 1;" ::: "memory")

__device__ __forceinline__ void mma_f16(float c[4],
                                        uint32_t a0, uint32_t a1, uint32_t a2, uint32_t a3,
                                        uint32_t b0, uint32_t b1) {
    asm volatile(
        "mma.sync.aligned.m16n8k16.row.col.f32.f16.f16.f32 "
        "{%0,%1,%2,%3}, {%4,%5,%6,%7}, {%8,%9}, {%0,%1,%2,%3};"
        : "+f"(c[0]), "+f"(c[1]), "+f"(c[2]), "+f"(c[3])
        : "r"(a0), "r"(a1), "r"(a2), "r"(a3), "r"(b0), "r"(b1));
}
#define LDSM4(r0, r1, r2, r3, addr) \
    asm volatile("ldmatrix.sync.aligned.m8n8.x4.shared.b16 {%0,%1,%2,%3}, [%4];" \
        : "=r"(r0), "=r"(r1), "=r"(r2), "=r"(r3) : "r"(addr))

enum { EP_NONE = 0, EP_SOFTPLUS };

__device__ __forceinline__ float sigm(float x) { return 1.0f / (1.0f + expf(-x)); }
__device__ __forceinline__ float sftp(float x) { return (x > 20.0f) ? x : log1pf(expf(x)); }

// ---------------------------------------------------------------------------
// fp16 GEMM (best-known config: ldmatrix, BK=64, 256 thr, warp 64x32,
// 3-stage cp.async, 2 CTA/SM).
// Modes on blockIdx.z:
//   Wz1 != nullptr : dual-weight (z=0: W->C ; z=1: Wz1->P1), same K range.
//   else P1 != nullptr : K-split  (z=1 reads at col offset K, extent K2 -> P1).
// Folded side-block (last bx, W2 != nullptr): C2 = A @ W2^T, N2=32.
// ---------------------------------------------------------------------------
template<int EP>
__global__ void __launch_bounds__(256, 2) gemm_h(
    const __half* __restrict__ A, const __half* __restrict__ W,
    const float* __restrict__ bias,
    float* __restrict__ C, __half* __restrict__ C16,
    int M, int N, int K, int K2, int lda, int ldw,
    const __half* __restrict__ W2, float* __restrict__ C2,
    float* __restrict__ P1, const __half* __restrict__ Wz1)
{
    constexpr int MT = 4, NT = 4;
    extern __shared__ uint32_t sm[];
    uint32_t* As = sm;
    uint32_t* Bs = sm + STAGES * ASTG;
    const uint32_t sbA = s2u(As), sbB = s2u(Bs);

    const int tid  = threadIdx.x;
    const int wid  = tid >> 5, lane = tid & 31;
    const int wm   = wid >> 2, wn = wid & 3;
    const int bm   = blockIdx.y << 7;
    const int bx   = blockIdx.x;
    const int bz   = blockIdx.z;

    const __half* Wsel;
    int koff, Kext;
    if (Wz1 != nullptr) {            // dual-weight mode
        Wsel = bz ? Wz1 : W;
        koff = 0;
        Kext = K;
    } else {                          // normal / K-split mode
        Wsel = W;
        koff = bz * K;
        Kext = bz ? K2 : K;
    }
    float* Cw = (bz == 1 && P1 != nullptr) ? P1 : C;

    const bool isbc = (W2 != nullptr) && (bx == (int)gridDim.x - 1);
    const int bn   = isbc ? 0 : (bx << 7);
    const int Nw   = isbc ? 32 : N;
    const __half* Wk = isbc ? W2 : Wsel;
    const int lr   = lane >> 2, lc = lane & 3;

    float acc[MT][NT][4];
    #pragma unroll
    for (int i = 0; i < MT; i++)
        #pragma unroll
        for (int j = 0; j < NT; j++)
            #pragma unroll
            for (int q = 0; q < 4; q++) acc[i][j][q] = 0.0f;

    const int row0 = tid >> 3;
    const int ch   = tid & 7;
    const int kh   = ch << 3;
    const int NS   = Kext >> 6;               // BK = 64

    const __half* abase = A + (size_t)(bm + row0) * lda + koff + kh;
    const uint32_t adst0 = sbA + (uint32_t)((row0 * SW + ch * 4) << 2);
    const uint32_t bdst0 = sbB + (uint32_t)((row0 * SW + ch * 4) << 2);
    constexpr uint32_t STGB = ASTG * 4;
    constexpr uint32_t ROWB = 32 * SW * 4;
    const size_t lda32 = (size_t)lda * 32;

    const __half* bbase[4];
    int bval[4];
    #pragma unroll
    for (int j = 0; j < 4; j++) {
        const int r = bn + row0 + 32 * j;
        bval[j]  = (r < Nw) ? 16 : 0;
        bbase[j] = Wk + (size_t)min(r, Nw - 1) * ldw + koff + kh;
    }

    auto issue = [&](int st, int k0) {
        const uint32_t da = adst0 + st * STGB;
        const uint32_t db = bdst0 + st * STGB;
        #pragma unroll
        for (int j = 0; j < 4; j++) cpa16(da + j * ROWB, abase + j * lda32 + k0, 16);
        #pragma unroll
        for (int j = 0; j < 4; j++) cpa16(db + j * ROWB, bbase[j] + k0, bval[j]);
        CP_COMMIT();
    };

    issue(0, 0);
    issue(1, 64);

    const int arow = lane & 15;
    const int acol = (lane >> 4) << 2;
    const uint32_t aoff = (uint32_t)(((wm * 64 + arow) * SW + acol) << 2);
    const int brw  = (lane & 7) + ((lane >> 4) << 3);
    const int bcl  = ((lane >> 3) & 1) << 2;
    const uint32_t boff = (uint32_t)(((wn * 32 + brw) * SW + bcl) << 2);
    constexpr uint32_t TMSTR = 16 * SW * 4;

    int buf = 0;
    for (int ks = 0; ks < NS; ks++) {
        CP_WAIT1();
        __syncthreads();

        if (ks + 2 < NS) {
            int nb = buf + 2; if (nb >= 3) nb -= 3;
            issue(nb, (ks + 2) << 6);
        } else CP_COMMIT();

        const uint32_t Abase = sbA + buf * STGB + aoff;
        const uint32_t Bbase = sbB + buf * STGB + boff;

        #pragma unroll
        for (int kc = 0; kc < 4; kc++) {
            uint32_t af[MT][4], bf[NT][2];
            #pragma unroll
            for (int tm = 0; tm < MT; tm++)
                LDSM4(af[tm][0], af[tm][1], af[tm][2], af[tm][3],
                      Abase + tm * TMSTR + kc * 32);
            #pragma unroll
            for (int tp = 0; tp < 2; tp++)
                LDSM4(bf[2*tp][0], bf[2*tp][1], bf[2*tp+1][0], bf[2*tp+1][1],
                      Bbase + tp * TMSTR + kc * 32);
            #pragma unroll
            for (int tm = 0; tm < MT; tm++)
                #pragma unroll
                for (int tn = 0; tn < NT; tn++)
                    mma_f16(acc[tm][tn], af[tm][0], af[tm][1], af[tm][2], af[tm][3],
                            bf[tn][0], bf[tn][1]);
        }
        if (++buf == 3) buf = 0;
    }

    if (isbc) {
        #pragma unroll
        for (int tm = 0; tm < MT; tm++) {
            const int row = bm + wm * 64 + tm * 16 + lr;
            #pragma unroll
            for (int tn = 0; tn < NT; tn++) {
                const int col = wn * 32 + tn * 8 + lc * 2;
                if (col < 32) {
                    *(float2*)(C2 + (size_t)row * 32 + col) =
                        make_float2(acc[tm][tn][0], acc[tm][tn][1]);
                    *(float2*)(C2 + (size_t)(row + 8) * 32 + col) =
                        make_float2(acc[tm][tn][2], acc[tm][tn][3]);
                }
            }
        }
        return;
    }

    #pragma unroll
    for (int tm = 0; tm < MT; tm++) {
        const int row = bm + wm * 64 + tm * 16 + lr;
        #pragma unroll
        for (int tn = 0; tn < NT; tn++) {
            const int col = bn + wn * 32 + tn * 8 + lc * 2;
            if (col < N) {
                #pragma unroll
                for (int hf = 0; hf < 2; hf++) {
                    const size_t o = (size_t)(row + hf * 8) * N + col;
                    float v0 = acc[tm][tn][hf * 2], v1 = acc[tm][tn][hf * 2 + 1];
                    if (EP == EP_NONE) {
                        *(float2*)(Cw + o) = make_float2(v0, v1);
                    } else { // EP_SOFTPLUS
                        const float2 bv2 = *(const float2*)(bias + col);
                        *(float2*)(C + o) = make_float2(sftp(v0 + bv2.x), sftp(v1 + bv2.y));
                    }
                }
            }
        }
    }
}

// ---------------------------------------------------------------------------
// Elementwise combiners for dual-weight GEMM outputs
// ---------------------------------------------------------------------------
// a = t_in * sigmoid(t_gt) ; a16 = fp16(a)   (n = ROWS*DIN)
__global__ void __launch_bounds__(256) gate_mul2_kernel()
{
    const size_t i = ((size_t)blockIdx.x * 256 + threadIdx.x) * 4;
    const float4 vi = *(const float4*)(g_g + i);
    const float4 vg = *(const float4*)(g_u + i);
    float4 v;
    v.x = vi.x * sigm(vg.x); v.y = vi.y * sigm(vg.y);
    v.z = vi.z * sigm(vg.z); v.w = vi.w * sigm(vg.w);
    *(float4*)(g_a + i) = v;
    __half2* o = (__half2*)(g_a16 + i);
    o[0] = __floats2half2_rn(v.x, v.y);
    o[1] = __floats2half2_rn(v.z, v.w);
}

// g16 = fp16(silu(gg) * uu)   (n = ROWS*FH)
__global__ void __launch_bounds__(256) silu_mul2_kernel()
{
    const size_t i = ((size_t)blockIdx.x * 256 + threadIdx.x) * 4;
    const float4 vg = *(const float4*)(g_g + i);
    const float4 vu = *(const float4*)(g_u + i);
    __half2* o = (__half2*)(g_g16 + i);
    o[0] = __floats2half2_rn(vg.x * sigm(vg.x) * vu.x, vg.y * sigm(vg.y) * vu.y);
    o[1] = __floats2half2_rn(vg.z * sigm(vg.z) * vu.z, vg.w * sigm(vg.w) * vu.w);
}

// ---------------------------------------------------------------------------
// Fused fp32->fp16 conversion of all 8 weight matrices in one launch.
// ---------------------------------------------------------------------------
struct CvtJobs {
    const float4* src[8];
    __half2* dst[8];
    int cum[9];
};

__global__ void __launch_bounds__(256) cvt_all_kernel(CvtJobs jobs)
{
    int i = blockIdx.x * 256 + threadIdx.x;
    if (i >= jobs.cum[8]) return;
    int j = 0;
    #pragma unroll
    for (int t = 1; t < 8; t++) j += (i >= jobs.cum[t]);
    const int li = i - jobs.cum[j];
    const float4 v = jobs.src[j][li];
    jobs.dst[j][2 * li]     = __floats2half2_rn(v.x, v.y);
    jobs.dst[j][2 * li + 1] = __floats2half2_rn(v.z, v.w);
}

// ---------------------------------------------------------------------------
// RMSNorm -> fp16 output
// ---------------------------------------------------------------------------
__global__ void __launch_bounds__(256) rmsnorm16_kernel(
    const float* __restrict__ x, const float* __restrict__ w, __half* __restrict__ out)
{
    __shared__ float red[8];
    const int row = blockIdx.x;
    const int tid = threadIdx.x;
    const float4 v = ((const float4*)(x + (size_t)row * DM))[tid];
    float s = v.x*v.x + v.y*v.y + v.z*v.z + v.w*v.w;
    #pragma unroll
    for (int o = 16; o; o >>= 1) s += __shfl_xor_sync(0xffffffffu, s, o);
    if ((tid & 31) == 0) red[tid >> 5] = s;
    __syncthreads();
    if (tid < 8) {
        float t = red[tid];
        #pragma unroll
        for (int o = 4; o; o >>= 1) t += __shfl_xor_sync(0xffu, t, o);
        if (tid == 0) red[0] = t;
    }
    __syncthreads();
    const float scale = rsqrtf(red[0] * (1.0f / DM) + 1e-6f);
    const float4 wv = ((const float4*)w)[tid];
    __half2* op = (__half2*)(out + (size_t)row * DM) + tid * 2;
    op[0] = __floats2half2_rn(v.x * scale * wv.x, v.y * scale * wv.y);
    op[1] = __floats2half2_rn(v.z * scale * wv.z, v.w * scale * wv.w);
}

// ---------------------------------------------------------------------------
// x2 = x + p0 + p1 ; h16 = fp16(rmsnorm(x2, w))
// ---------------------------------------------------------------------------
__global__ void __launch_bounds__(256) combine_norm_kernel(
    const float* __restrict__ x, const float* __restrict__ w,
    float* __restrict__ x2, __half* __restrict__ h16)
{
    __shared__ float red[8];
    const int row = blockIdx.x;
    const int tid = threadIdx.x;
    const size_t o = (size_t)row * DM / 4 + tid;
    const float4 xv = ((const float4*)x)[o];
    const float4 p0 = ((const float4*)g_p0)[o];
    const float4 p1 = ((const float4*)g_p1)[o];
    float4 v;
    v.x = xv.x + p0.x + p1.x; v.y = xv.y + p0.y + p1.y;
    v.z = xv.z + p0.z + p1.z; v.w = xv.w + p0.w + p1.w;
    ((float4*)x2)[o] = v;
    float s = v.x*v.x + v.y*v.y + v.z*v.z + v.w*v.w;
    #pragma unroll
    for (int of = 16; of; of >>= 1) s += __shfl_xor_sync(0xffffffffu, s, of);
    if ((tid & 31) == 0) red[tid >> 5] = s;
    __syncthreads();
    if (tid < 8) {
        float t = red[tid];
        #pragma unroll
        for (int of = 4; of; of >>= 1) t += __shfl_xor_sync(0xffu, t, of);
        if (tid == 0) red[0] = t;
    }
    __syncthreads();
    const float scale = rsqrtf(red[0] * (1.0f / DM) + 1e-6f);
    const float4 wv = ((const float4*)w)[tid];
    __half2* op = (__half2*)(h16 + (size_t)row * DM) + tid * 2;
    op[0] = __floats2half2_rn(v.x * scale * wv.x, v.y * scale * wv.y);
    op[1] = __floats2half2_rn(v.z * scale * wv.z, v.w * scale * wv.w);
}

// out = x2 + p0 + p1
__global__ void __launch_bounds__(256) combine_add_kernel(
    const float* __restrict__ x2, float* __restrict__ out)
{
    const size_t i = (size_t)blockIdx.x * 256 + threadIdx.x;
    const float4 a = ((const float4*)x2)[i];
    const float4 p0 = ((const float4*)g_p0)[i];
    const float4 p1 = ((const float4*)g_p1)[i];
    float4 v;
    v.x = a.x + p0.x + p1.x; v.y = a.y + p0.y + p1.y;
    v.z = a.z + p0.z + p1.z; v.w = a.w + p0.w + p1.w;
    ((float4*)out)[i] = v;
}

// ---------------------------------------------------------------------------
// Selective scan (16 lanes per channel) -> y16 fp16
// ---------------------------------------------------------------------------
__global__ void __launch_bounds__(256) scan_kernel(
    const float* __restrict__ A_log, const float* __restrict__ Dp)
{
    const int tid = threadIdx.x;
    const int ch  = blockIdx.x * 16 + (tid >> 4);
    const int n   = tid & 15;
    const int b   = ch / DIN;
    const int e   = ch % DIN;

    const float An  = -__expf(A_log[(size_t)e * NST + n]);
    const float dpe = Dp[e];

    const float* dtp = g_b  + (size_t)b * SEQ * DIN + e;
    const float* zp  = g_a  + (size_t)b * SEQ * DIN + e;
    const float* bcp = g_bc + (size_t)b * SEQ * 32;
    __half*      yp  = g_y16 + (size_t)b * SEQ * DIN + e;

    float state = 0.0f;
    #pragma unroll 4
    for (int t = 0; t < SEQ; t++) {
        const float dtv = __ldg(dtp + (size_t)t * DIN);
        const float zv  = __ldg(zp  + (size_t)t * DIN);
        const float Bn  = bcp[t * 32 + n];
        const float Cn  = bcp[t * 32 + 16 + n];
        state = __expf(dtv * An) * state + dtv * zv * Bn;
        float s = state * Cn;
        s += __shfl_xor_sync(0xffffffffu, s, 8);
        s += __shfl_xor_sync(0xffffffffu, s, 4);
        s += __shfl_xor_sync(0xffffffffu, s, 2);
        s += __shfl_xor_sync(0xffffffffu, s, 1);
        if (n == 0) yp[(size_t)t * DIN] = __float2half_rn(s + zv * dpe);
    }
}

// ---------------------------------------------------------------------------
// Launch
// ---------------------------------------------------------------------------
extern "C" void kernel_launch(void* const* d_in, const int* in_sizes, int n_in,
                              void* d_out, int out_size)
{
    const float* x          = (const float*)d_in[0];
    const float* norm1_w    = (const float*)d_in[1];
    const float* in_proj_w  = (const float*)d_in[2];
    const float* gate_proj_w= (const float*)d_in[3];
    const float* dt_w       = (const float*)d_in[4];
    const float* dt_b       = (const float*)d_in[5];
    const float* x_proj_w   = (const float*)d_in[6];
    const float* A_log      = (const float*)d_in[7];
    const float* Dp         = (const float*)d_in[8];
    const float* out_proj_w = (const float*)d_in[9];
    const float* ffn_norm_w = (const float*)d_in[10];
    const float* ffn_gate_w = (const float*)d_in[11];
    const float* ffn_up_w   = (const float*)d_in[12];
    const float* ffn_down_w = (const float*)d_in[13];
    float* out = (float*)d_out;

    float *bb, *x2, *bc, *p0, *p1, *gg, *uu;
    __half *h16, *y16, *g16;
    __half *win, *wgt, *wdt, *wx, *wout, *wfg, *wfu, *wfd;
    cudaGetSymbolAddress((void**)&bb,  g_b);
    cudaGetSymbolAddress((void**)&x2,  g_x2);
    cudaGetSymbolAddress((void**)&bc,  g_bc);
    cudaGetSymbolAddress((void**)&p0,  g_p0);
    cudaGetSymbolAddress((void**)&p1,  g_p1);
    cudaGetSymbolAddress((void**)&gg,  g_g);
    cudaGetSymbolAddress((void**)&uu,  g_u);
    cudaGetSymbolAddress((void**)&h16, g_h16);
    cudaGetSymbolAddress((void**)&y16, g_y16);
    cudaGetSymbolAddress((void**)&g16, g_g16);
    cudaGetSymbolAddress((void**)&win, g_win16);
    cudaGetSymbolAddress((void**)&wgt, g_wgt16);
    cudaGetSymbolAddress((void**)&wdt, g_wdt16);
    cudaGetSymbolAddress((void**)&wx,  g_wx16);
    cudaGetSymbolAddress((void**)&wout,g_wout16);
    cudaGetSymbolAddress((void**)&wfg, g_wfg16);
    cudaGetSymbolAddress((void**)&wfu, g_wfu16);
    cudaGetSymbolAddress((void**)&wfd, g_wfd16);
    __half* a16;
    cudaGetSymbolAddress((void**)&a16, g_a16);

    const int SMEM = STAGES * ASTG * 4 * 2;   // 110592 bytes

    cudaFuncSetAttribute((const void*)gemm_h<EP_NONE>,     cudaFuncAttributeMaxDynamicSharedMemorySize, SMEM);
    cudaFuncSetAttribute((const void*)gemm_h<EP_SOFTPLUS>, cudaFuncAttributeMaxDynamicSharedMemorySize, SMEM);

    const dim3 blk256(256);

    // 0. Convert all weights to fp16 in one launch
    {
        CvtJobs jobs;
        const float* srcs[8] = {in_proj_w, gate_proj_w, dt_w, x_proj_w,
                                out_proj_w, ffn_gate_w, ffn_up_w, ffn_down_w};
        __half* dsts[8] = {win, wgt, wdt, wx, wout, wfg, wfu, wfd};
        const int ns[8] = {DIN*DM, DIN*DM, DIN*DIN, 2*NST*DIN,
                           DM*DIN, FH*DM, FH*DM, DM*FH};
        int cum = 0;
        for (int j = 0; j < 8; j++) {
            jobs.src[j] = (const float4*)srcs[j];
            jobs.dst[j] = (__half2*)dsts[j];
            jobs.cum[j] = cum;
            cum += ns[j] / 4;
        }
        jobs.cum[8] = cum;
        cvt_all_kernel<<<(cum + 255) / 256, blk256>>>(jobs);
    }

    // 1. h16 = fp16(rmsnorm(x))
    rmsnorm16_kernel<<<ROWS, blk256>>>(x, norm1_w, h16);

    // 2. Dual-weight launch: z=0 -> gg = h@win^T ; z=1 -> uu = h@wgt^T.
    //    Then a = gg * sigmoid(uu) (fp32 + fp16).
    gemm_h<EP_NONE><<<dim3(DIN/128, ROWS/128, 2), blk256, SMEM>>>(
        h16, win, nullptr, gg, nullptr, ROWS, DIN, DM, 0, DM, DM,
        nullptr, nullptr, uu, wgt);
    gate_mul2_kernel<<<(ROWS * DIN) / 1024, blk256>>>();

    // 3. dt = softplus(z @ dt_w^T + dt_b)  [+ folded BC = z @ x_proj^T]
    gemm_h<EP_SOFTPLUS><<<dim3(DIN/128 + 1, ROWS/128), blk256, SMEM>>>(
        a16, wdt, dt_b, bb, nullptr, ROWS, DIN, DIN, 0, DIN, DIN,
        wx, bc, nullptr, nullptr);

    // 4. scan -> y16
    scan_kernel<<<(BATCH * DIN) / 16, blk256>>>(A_log, Dp);

    // 5. p0/p1 = y @ out_proj^T (K-split); x2 = x + p0 + p1 ; h16 = fp16(rmsnorm(x2))
    gemm_h<EP_NONE><<<dim3(DM/128, ROWS/128, 2), blk256, SMEM>>>(
        y16, wout, nullptr, p0, nullptr, ROWS, DM, DIN/2, DIN/2, DIN, DIN,
        nullptr, nullptr, p1, nullptr);
    combine_norm_kernel<<<ROWS, blk256>>>(x, ffn_norm_w, x2, h16);

    // 6. Dual-weight FFN launch: z=0 -> gg = hn@Wg^T ; z=1 -> uu = hn@Wu^T.
    //    Then g16 = fp16(silu(gg) * uu).
    gemm_h<EP_NONE><<<dim3((FH+127)/128, ROWS/128, 2), blk256, SMEM>>>(
        h16, wfg, nullptr, gg, nullptr, ROWS, FH, DM, 0, DM, DM,
        nullptr, nullptr, uu, wfu);
    silu_mul2_kernel<<<(ROWS * FH) / 1024, blk256>>>();

    // 7. p0/p1 = g16 @ Wd^T (uneven K-split 1408/1344); out = x2 + p0 + p1
    gemm_h<EP_NONE><<<dim3(DM/128, ROWS/128, 2), blk256, SMEM>>>(
        g16, wfd, nullptr, p0, nullptr, ROWS, DM, 1408, 1344, FH, FH,
        nullptr, nullptr, p1, nullptr);
    combine_add_kernel<<<(ROWS * DM) / 1024, blk256>>>(x2, out);
}

// round 17
// speedup vs baseline: 1.2549x; 1.0383x over previous
#include <cuda_runtime.h>
#include <cuda_fp16.h>
#include <math.h>
#include <stdint.h>

// Problem dims
constexpr int BATCH = 2;
constexpr int SEQ   = 1024;
constexpr int DM    = 1024;
constexpr int DIN   = 2048;
constexpr int NST   = 16;
constexpr int FH    = 2752;
constexpr int ROWS  = BATCH * SEQ;  // 2048

// fp32 scratch
__device__ float g_b [ROWS * DIN];    // dt
__device__ float g_x2[ROWS * DM];     // residual accumulator (RED target)
__device__ float g_bc[ROWS * 2 * NST];
__device__ float g_g [ROWS * FH];     // raw gemm output 1
__device__ float g_u [ROWS * FH];     // raw gemm output 2
// fp16 activations
__device__ __half g_h16[ROWS * DM];
__device__ __half g_a16[ROWS * DIN];  // z (scan reads this)
__device__ __half g_y16[ROWS * DIN];
__device__ __half g_g16[ROWS * FH];
// fp16 weights
__device__ __half g_win16 [DIN * DM];
__device__ __half g_wgt16 [DIN * DM];
__device__ __half g_wdt16 [DIN * DIN];
__device__ __half g_wx16  [2 * NST * DIN];
__device__ __half g_wout16[DM * DIN];
__device__ __half g_wfg16 [FH * DM];
__device__ __half g_wfu16 [FH * DM];
__device__ __half g_wfd16 [DM * FH];

constexpr int SW   = 36;             // smem row stride in 4-byte words
constexpr int ASTG = 128 * SW;
constexpr int STAGES = 3;

__device__ __forceinline__ uint32_t s2u(const void* p) {
    uint32_t a;
    asm("{ .reg .u64 t; cvta.to.shared.u64 t, %1; cvt.u32.u64 %0, t; }" : "=r"(a) : "l"(p));
    return a;
}
__device__ __forceinline__ void cpa16(uint32_t dst, const __half* src, int szbytes) {
    asm volatile("cp.async.cg.shared.global [%0], [%1], 16, %2;"
                 :: "r"(dst), "l"(src), "r"(szbytes));
}
#define CP_COMMIT() asm volatile("cp.async.commit_group;" ::: "memory")
#define CP_WAIT1()  asm volatile("cp.async.wait_group 1;" ::: "memory")

__device__ __forceinline__ void mma_f16(float c[4],
                                        uint32_t a0, uint32_t a1, uint32_t a2, uint32_t a3,
                                        uint32_t b0, uint32_t b1) {
    asm volatile(
        "mma.sync.aligned.m16n8k16.row.col.f32.f16.f16.f32 "
        "{%0,%1,%2,%3}, {%4,%5,%6,%7}, {%8,%9}, {%0,%1,%2,%3};"
        : "+f"(c[0]), "+f"(c[1]), "+f"(c[2]), "+f"(c[3])
        : "r"(a0), "r"(a1), "r"(a2), "r"(a3), "r"(b0), "r"(b1));
}
#define LDSM4(r0, r1, r2, r3, addr) \
    asm volatile("ldmatrix.sync.aligned.m8n8.x4.shared.b16 {%0,%1,%2,%3}, [%4];" \
        : "=r"(r0), "=r"(r1), "=r"(r2), "=r"(r3) : "r"(addr))

enum { EP_NONE = 0, EP_SOFTPLUS, EP_RED };

__device__ __forceinline__ float sigm(float x) { return 1.0f / (1.0f + expf(-x)); }
__device__ __forceinline__ float sftp(float x) { return (x > 20.0f) ? x : log1pf(expf(x)); }

// ---------------------------------------------------------------------------
// fp16 GEMM (ldmatrix, BK=64, 256 thr 8 warps 2x4, warp 64x32, 3-stage
// cp.async, 2 CTA/SM).
// Modes:
//   Wz1 != nullptr : dual-weight (z=0: W->C ; z=1: Wz1->P1), same K range.
//   K2 > 0         : K-split (z=1 reads col offset K, extent K2).  With
//                    EP_RED both halves atomically accumulate into C.
// Folded side-block (last bx, W2 != nullptr): C2 = A @ W2^T, N2=32.
// ---------------------------------------------------------------------------
template<int EP>
__global__ void __launch_bounds__(256, 2) gemm_h(
    const __half* __restrict__ A, const __half* __restrict__ W,
    const float* __restrict__ bias,
    float* __restrict__ C, __half* __restrict__ C16,
    int M, int N, int K, int K2, int lda, int ldw,
    const __half* __restrict__ W2, float* __restrict__ C2,
    float* __restrict__ P1, const __half* __restrict__ Wz1)
{
    constexpr int MT = 4, NT = 4;
    extern __shared__ uint32_t sm[];
    uint32_t* As = sm;
    uint32_t* Bs = sm + STAGES * ASTG;
    const uint32_t sbA = s2u(As), sbB = s2u(Bs);

    const int tid  = threadIdx.x;
    const int wid  = tid >> 5, lane = tid & 31;
    const int wm   = wid >> 2, wn = wid & 3;
    const int bm   = blockIdx.y << 7;
    const int bx   = blockIdx.x;
    const int bz   = blockIdx.z;

    const __half* Wsel;
    int koff, Kext;
    if (Wz1 != nullptr) {             // dual-weight mode
        Wsel = bz ? Wz1 : W;
        koff = 0;
        Kext = K;
    } else {                          // normal / K-split mode
        Wsel = W;
        koff = bz * K;
        Kext = bz ? K2 : K;
    }
    float* Cw = (Wz1 != nullptr && bz == 1) ? P1 : C;

    const bool isbc = (W2 != nullptr) && (bx == (int)gridDim.x - 1);
    const int bn   = isbc ? 0 : (bx << 7);
    const int Nw   = isbc ? 32 : N;
    const __half* Wk = isbc ? W2 : Wsel;
    const int lr   = lane >> 2, lc = lane & 3;

    float acc[MT][NT][4];
    #pragma unroll
    for (int i = 0; i < MT; i++)
        #pragma unroll
        for (int j = 0; j < NT; j++)
            #pragma unroll
            for (int q = 0; q < 4; q++) acc[i][j][q] = 0.0f;

    const int row0 = tid >> 3;
    const int ch   = tid & 7;
    const int kh   = ch << 3;
    const int NS   = Kext >> 6;               // BK = 64

    const __half* abase = A + (size_t)(bm + row0) * lda + koff + kh;
    const uint32_t adst0 = sbA + (uint32_t)((row0 * SW + ch * 4) << 2);
    const uint32_t bdst0 = sbB + (uint32_t)((row0 * SW + ch * 4) << 2);
    constexpr uint32_t STGB = ASTG * 4;
    constexpr uint32_t ROWB = 32 * SW * 4;
    const size_t lda32 = (size_t)lda * 32;

    const __half* bbase[4];
    int bval[4];
    #pragma unroll
    for (int j = 0; j < 4; j++) {
        const int r = bn + row0 + 32 * j;
        bval[j]  = (r < Nw) ? 16 : 0;
        bbase[j] = Wk + (size_t)min(r, Nw - 1) * ldw + koff + kh;
    }

    auto issue = [&](int st, int k0) {
        const uint32_t da = adst0 + st * STGB;
        const uint32_t db = bdst0 + st * STGB;
        #pragma unroll
        for (int j = 0; j < 4; j++) cpa16(da + j * ROWB, abase + j * lda32 + k0, 16);
        #pragma unroll
        for (int j = 0; j < 4; j++) cpa16(db + j * ROWB, bbase[j] + k0, bval[j]);
        CP_COMMIT();
    };

    issue(0, 0);
    issue(1, 64);

    const int arow = lane & 15;
    const int acol = (lane >> 4) << 2;
    const uint32_t aoff = (uint32_t)(((wm * 64 + arow) * SW + acol) << 2);
    const int brw  = (lane & 7) + ((lane >> 4) << 3);
    const int bcl  = ((lane >> 3) & 1) << 2;
    const uint32_t boff = (uint32_t)(((wn * 32 + brw) * SW + bcl) << 2);
    constexpr uint32_t TMSTR = 16 * SW * 4;

    int buf = 0;
    for (int ks = 0; ks < NS; ks++) {
        CP_WAIT1();
        __syncthreads();

        if (ks + 2 < NS) {
            int nb = buf + 2; if (nb >= 3) nb -= 3;
            issue(nb, (ks + 2) << 6);
        } else CP_COMMIT();

        const uint32_t Abase = sbA + buf * STGB + aoff;
        const uint32_t Bbase = sbB + buf * STGB + boff;

        #pragma unroll
        for (int kc = 0; kc < 4; kc++) {
            uint32_t af[MT][4], bf[NT][2];
            #pragma unroll
            for (int tm = 0; tm < MT; tm++)
                LDSM4(af[tm][0], af[tm][1], af[tm][2], af[tm][3],
                      Abase + tm * TMSTR + kc * 32);
            #pragma unroll
            for (int tp = 0; tp < 2; tp++)
                LDSM4(bf[2*tp][0], bf[2*tp][1], bf[2*tp+1][0], bf[2*tp+1][1],
                      Bbase + tp * TMSTR + kc * 32);
            #pragma unroll
            for (int tm = 0; tm < MT; tm++)
                #pragma unroll
                for (int tn = 0; tn < NT; tn++)
                    mma_f16(acc[tm][tn], af[tm][0], af[tm][1], af[tm][2], af[tm][3],
                            bf[tn][0], bf[tn][1]);
        }
        if (++buf == 3) buf = 0;
    }

    if (isbc) {
        #pragma unroll
        for (int tm = 0; tm < MT; tm++) {
            const int row = bm + wm * 64 + tm * 16 + lr;
            #pragma unroll
            for (int tn = 0; tn < NT; tn++) {
                const int col = wn * 32 + tn * 8 + lc * 2;
                if (col < 32) {
                    *(float2*)(C2 + (size_t)row * 32 + col) =
                        make_float2(acc[tm][tn][0], acc[tm][tn][1]);
                    *(float2*)(C2 + (size_t)(row + 8) * 32 + col) =
                        make_float2(acc[tm][tn][2], acc[tm][tn][3]);
                }
            }
        }
        return;
    }

    #pragma unroll
    for (int tm = 0; tm < MT; tm++) {
        const int row = bm + wm * 64 + tm * 16 + lr;
        #pragma unroll
        for (int tn = 0; tn < NT; tn++) {
            const int col = bn + wn * 32 + tn * 8 + lc * 2;
            if (col < N) {
                #pragma unroll
                for (int hf = 0; hf < 2; hf++) {
                    const size_t o = (size_t)(row + hf * 8) * N + col;
                    float v0 = acc[tm][tn][hf * 2], v1 = acc[tm][tn][hf * 2 + 1];
                    if (EP == EP_NONE) {
                        *(float2*)(Cw + o) = make_float2(v0, v1);
                    } else if (EP == EP_SOFTPLUS) {
                        const float2 bv2 = *(const float2*)(bias + col);
                        *(float2*)(C + o) = make_float2(sftp(v0 + bv2.x), sftp(v1 + bv2.y));
                    } else { // EP_RED: accumulate onto pre-seeded destination
                        atomicAdd(C + o,     v0);
                        atomicAdd(C + o + 1, v1);
                    }
                }
            }
        }
    }
}

// ---------------------------------------------------------------------------
// a16 = fp16(t_in * sigmoid(t_gt))   (n = ROWS*DIN)
// ---------------------------------------------------------------------------
__global__ void __launch_bounds__(256) gate_mul2_kernel()
{
    const size_t i = ((size_t)blockIdx.x * 256 + threadIdx.x) * 4;
    const float4 vi = *(const float4*)(g_g + i);
    const float4 vg = *(const float4*)(g_u + i);
    __half2* o = (__half2*)(g_a16 + i);
    o[0] = __floats2half2_rn(vi.x * sigm(vg.x), vi.y * sigm(vg.y));
    o[1] = __floats2half2_rn(vi.z * sigm(vg.z), vi.w * sigm(vg.w));
}

// g16 = fp16(silu(gg) * uu)   (n = ROWS*FH)
__global__ void __launch_bounds__(256) silu_mul2_kernel()
{
    const size_t i = ((size_t)blockIdx.x * 256 + threadIdx.x) * 4;
    const float4 vg = *(const float4*)(g_g + i);
    const float4 vu = *(const float4*)(g_u + i);
    __half2* o = (__half2*)(g_g16 + i);
    o[0] = __floats2half2_rn(vg.x * sigm(vg.x) * vu.x, vg.y * sigm(vg.y) * vu.y);
    o[1] = __floats2half2_rn(vg.z * sigm(vg.z) * vu.z, vg.w * sigm(vg.w) * vu.w);
}

// ---------------------------------------------------------------------------
// Fused fp32->fp16 conversion of all 8 weight matrices in one launch.
// ---------------------------------------------------------------------------
struct CvtJobs {
    const float4* src[8];
    __half2* dst[8];
    int cum[9];
};

__global__ void __launch_bounds__(256) cvt_all_kernel(CvtJobs jobs)
{
    int i = blockIdx.x * 256 + threadIdx.x;
    if (i >= jobs.cum[8]) return;
    int j = 0;
    #pragma unroll
    for (int t = 1; t < 8; t++) j += (i >= jobs.cum[t]);
    const int li = i - jobs.cum[j];
    const float4 v = jobs.src[j][li];
    jobs.dst[j][2 * li]     = __floats2half2_rn(v.x, v.y);
    jobs.dst[j][2 * li + 1] = __floats2half2_rn(v.z, v.w);
}

// ---------------------------------------------------------------------------
// RMSNorm -> fp16 output
// ---------------------------------------------------------------------------
__global__ void __launch_bounds__(256) rmsnorm16_kernel(
    const float* __restrict__ x, const float* __restrict__ w, __half* __restrict__ out)
{
    __shared__ float red[8];
    const int row = blockIdx.x;
    const int tid = threadIdx.x;
    const float4 v = ((const float4*)(x + (size_t)row * DM))[tid];
    float s = v.x*v.x + v.y*v.y + v.z*v.z + v.w*v.w;
    #pragma unroll
    for (int o = 16; o; o >>= 1) s += __shfl_xor_sync(0xffffffffu, s, o);
    if ((tid & 31) == 0) red[tid >> 5] = s;
    __syncthreads();
    if (tid < 8) {
        float t = red[tid];
        #pragma unroll
        for (int o = 4; o; o >>= 1) t += __shfl_xor_sync(0xffu, t, o);
        if (tid == 0) red[0] = t;
    }
    __syncthreads();
    const float scale = rsqrtf(red[0] * (1.0f / DM) + 1e-6f);
    const float4 wv = ((const float4*)w)[tid];
    __half2* op = (__half2*)(out + (size_t)row * DM) + tid * 2;
    op[0] = __floats2half2_rn(v.x * scale * wv.x, v.y * scale * wv.y);
    op[1] = __floats2half2_rn(v.z * scale * wv.z, v.w * scale * wv.w);
}

// ---------------------------------------------------------------------------
// x2 already holds x + out_proj(y) (RED-accumulated).  h16 = fp16(rmsnorm(x2));
// also seed out = x2 for the down-proj RED accumulation.
// ---------------------------------------------------------------------------
__global__ void __launch_bounds__(256) norm_seed_kernel(
    const float* __restrict__ x2, const float* __restrict__ w,
    float* __restrict__ outseed, __half* __restrict__ h16)
{
    __shared__ float red[8];
    const int row = blockIdx.x;
    const int tid = threadIdx.x;
    const size_t o = (size_t)row * DM / 4 + tid;
    const float4 v = ((const float4*)x2)[o];
    ((float4*)outseed)[o] = v;
    float s = v.x*v.x + v.y*v.y + v.z*v.z + v.w*v.w;
    #pragma unroll
    for (int of = 16; of; of >>= 1) s += __shfl_xor_sync(0xffffffffu, s, of);
    if ((tid & 31) == 0) red[tid >> 5] = s;
    __syncthreads();
    if (tid < 8) {
        float t = red[tid];
        #pragma unroll
        for (int of = 4; of; of >>= 1) t += __shfl_xor_sync(0xffu, t, of);
        if (tid == 0) red[0] = t;
    }
    __syncthreads();
    const float scale = rsqrtf(red[0] * (1.0f / DM) + 1e-6f);
    const float4 wv = ((const float4*)w)[tid];
    __half2* op = (__half2*)(h16 + (size_t)row * DM) + tid * 2;
    op[0] = __floats2half2_rn(v.x * scale * wv.x, v.y * scale * wv.y);
    op[1] = __floats2half2_rn(v.z * scale * wv.z, v.w * scale * wv.w);
}

// ---------------------------------------------------------------------------
// Selective scan (16 lanes per channel); z from fp16 a16 -> y16 fp16
// ---------------------------------------------------------------------------
__global__ void __launch_bounds__(256) scan_kernel(
    const float* __restrict__ A_log, const float* __restrict__ Dp)
{
    const int tid = threadIdx.x;
    const int ch  = blockIdx.x * 16 + (tid >> 4);
    const int n   = tid & 15;
    const int b   = ch / DIN;
    const int e   = ch % DIN;

    const float An  = -__expf(A_log[(size_t)e * NST + n]);
    const float dpe = Dp[e];

    const float*  dtp = g_b   + (size_t)b * SEQ * DIN + e;
    const __half* zp  = g_a16 + (size_t)b * SEQ * DIN + e;
    const float*  bcp = g_bc  + (size_t)b * SEQ * 32;
    __half*       yp  = g_y16 + (size_t)b * SEQ * DIN + e;

    float state = 0.0f;
    #pragma unroll 4
    for (int t = 0; t < SEQ; t++) {
        const float dtv = __ldg(dtp + (size_t)t * DIN);
        const float zv  = __half2float(__ldg(zp + (size_t)t * DIN));
        const float Bn  = bcp[t * 32 + n];
        const float Cn  = bcp[t * 32 + 16 + n];
        state = __expf(dtv * An) * state + dtv * zv * Bn;
        float s = state * Cn;
        s += __shfl_xor_sync(0xffffffffu, s, 8);
        s += __shfl_xor_sync(0xffffffffu, s, 4);
        s += __shfl_xor_sync(0xffffffffu, s, 2);
        s += __shfl_xor_sync(0xffffffffu, s, 1);
        if (n == 0) yp[(size_t)t * DIN] = __float2half_rn(s + zv * dpe);
    }
}

// ---------------------------------------------------------------------------
// Launch
// ---------------------------------------------------------------------------
extern "C" void kernel_launch(void* const* d_in, const int* in_sizes, int n_in,
                              void* d_out, int out_size)
{
    const float* x          = (const float*)d_in[0];
    const float* norm1_w    = (const float*)d_in[1];
    const float* in_proj_w  = (const float*)d_in[2];
    const float* gate_proj_w= (const float*)d_in[3];
    const float* dt_w       = (const float*)d_in[4];
    const float* dt_b       = (const float*)d_in[5];
    const float* x_proj_w   = (const float*)d_in[6];
    const float* A_log      = (const float*)d_in[7];
    const float* Dp         = (const float*)d_in[8];
    const float* out_proj_w = (const float*)d_in[9];
    const float* ffn_norm_w = (const float*)d_in[10];
    const float* ffn_gate_w = (const float*)d_in[11];
    const float* ffn_up_w   = (const float*)d_in[12];
    const float* ffn_down_w = (const float*)d_in[13];
    float* out = (float*)d_out;

    float *bb, *x2, *bc, *gg, *uu;
    __half *h16, *a16, *y16, *g16;
    __half *win, *wgt, *wdt, *wx, *wout, *wfg, *wfu, *wfd;
    cudaGetSymbolAddress((void**)&bb,  g_b);
    cudaGetSymbolAddress((void**)&x2,  g_x2);
    cudaGetSymbolAddress((void**)&bc,  g_bc);
    cudaGetSymbolAddress((void**)&gg,  g_g);
    cudaGetSymbolAddress((void**)&uu,  g_u);
    cudaGetSymbolAddress((void**)&h16, g_h16);
    cudaGetSymbolAddress((void**)&a16, g_a16);
    cudaGetSymbolAddress((void**)&y16, g_y16);
    cudaGetSymbolAddress((void**)&g16, g_g16);
    cudaGetSymbolAddress((void**)&win, g_win16);
    cudaGetSymbolAddress((void**)&wgt, g_wgt16);
    cudaGetSymbolAddress((void**)&wdt, g_wdt16);
    cudaGetSymbolAddress((void**)&wx,  g_wx16);
    cudaGetSymbolAddress((void**)&wout,g_wout16);
    cudaGetSymbolAddress((void**)&wfg, g_wfg16);
    cudaGetSymbolAddress((void**)&wfu, g_wfu16);
    cudaGetSymbolAddress((void**)&wfd, g_wfd16);

    const int SMEM = STAGES * ASTG * 4 * 2;   // 110592 bytes

    cudaFuncSetAttribute((const void*)gemm_h<EP_NONE>,     cudaFuncAttributeMaxDynamicSharedMemorySize, SMEM);
    cudaFuncSetAttribute((const void*)gemm_h<EP_SOFTPLUS>, cudaFuncAttributeMaxDynamicSharedMemorySize, SMEM);
    cudaFuncSetAttribute((const void*)gemm_h<EP_RED>,      cudaFuncAttributeMaxDynamicSharedMemorySize, SMEM);

    const dim3 blk256(256);

    // 0. Convert all weights to fp16 in one launch; seed x2 = x.
    {
        CvtJobs jobs;
        const float* srcs[8] = {in_proj_w, gate_proj_w, dt_w, x_proj_w,
                                out_proj_w, ffn_gate_w, ffn_up_w, ffn_down_w};
        __half* dsts[8] = {win, wgt, wdt, wx, wout, wfg, wfu, wfd};
        const int ns[8] = {DIN*DM, DIN*DM, DIN*DIN, 2*NST*DIN,
                           DM*DIN, FH*DM, FH*DM, DM*FH};
        int cum = 0;
        for (int j = 0; j < 8; j++) {
            jobs.src[j] = (const float4*)srcs[j];
            jobs.dst[j] = (__half2*)dsts[j];
            jobs.cum[j] = cum;
            cum += ns[j] / 4;
        }
        jobs.cum[8] = cum;
        cvt_all_kernel<<<(cum + 255) / 256, blk256>>>(jobs);
    }
    cudaMemcpyAsync(x2, x, (size_t)ROWS * DM * sizeof(float), cudaMemcpyDeviceToDevice);

    // 1. h16 = fp16(rmsnorm(x))
    rmsnorm16_kernel<<<ROWS, blk256>>>(x, norm1_w, h16);

    // 2. Dual-weight launch: z=0 -> gg = h@win^T ; z=1 -> uu = h@wgt^T.
    //    Then a16 = fp16(gg * sigmoid(uu)).
    gemm_h<EP_NONE><<<dim3(DIN/128, ROWS/128, 2), blk256, SMEM>>>(
        h16, win, nullptr, gg, nullptr, ROWS, DIN, DM, 0, DM, DM,
        nullptr, nullptr, uu, wgt);
    gate_mul2_kernel<<<(ROWS * DIN) / 1024, blk256>>>();

    // 3. dt = softplus(z @ dt_w^T + dt_b)  [+ folded BC = z @ x_proj^T]
    gemm_h<EP_SOFTPLUS><<<dim3(DIN/128 + 1, ROWS/128), blk256, SMEM>>>(
        a16, wdt, dt_b, bb, nullptr, ROWS, DIN, DIN, 0, DIN, DIN,
        wx, bc, nullptr, nullptr);

    // 4. scan -> y16
    scan_kernel<<<(BATCH * DIN) / 16, blk256>>>(A_log, Dp);

    // 5. x2 += y @ out_proj^T (K-split, RED accumulate onto x2 = x)
    gemm_h<EP_RED><<<dim3(DM/128, ROWS/128, 2), blk256, SMEM>>>(
        y16, wout, nullptr, x2, nullptr, ROWS, DM, DIN/2, DIN/2, DIN, DIN,
        nullptr, nullptr, nullptr, nullptr);

    // 6. h16 = fp16(rmsnorm(x2)); seed out = x2
    norm_seed_kernel<<<ROWS, blk256>>>(x2, ffn_norm_w, out, h16);

    // 7. Dual-weight FFN: z=0 -> gg = hn@Wg^T ; z=1 -> uu = hn@Wu^T;
    //    g16 = fp16(silu(gg) * uu)
    gemm_h<EP_NONE><<<dim3((FH+127)/128, ROWS/128, 2), blk256, SMEM>>>(
        h16, wfg, nullptr, gg, nullptr, ROWS, FH, DM, 0, DM, DM,
        nullptr, nullptr, uu, wfu);
    silu_mul2_kernel<<<(ROWS * FH) / 1024, blk256>>>();

    // 8. out += g16 @ Wd^T (uneven K-split 1408/1344, RED accumulate)
    gemm_h<EP_RED><<<dim3(DM/128, ROWS/128, 2), blk256, SMEM>>>(
        g16, wfd, nullptr, out, nullptr, ROWS, DM, 1408, 1344, FH, FH,
        nullptr, nullptr, nullptr, nullptr);
}